// round 9
// baseline (speedup 1.0000x reference)
#include <cuda_runtime.h>
#include <math.h>
#include <stdint.h>
#include <stddef.h>

#define BDIM 128
#define TDIM 512
#define IDIM 32
#define HDIM 1024
#define GDIM 4096          // 4*H
#define BH   (BDIM*HDIM)
#define NBLK 128           // persistent grid: <=148 SMs -> all co-resident
#define NTHR 512           // 2 K-groups x 256

// ---------------- static device scratch (no allocations anywhere) ----------------
static __device__ float g_xg[(size_t)BDIM * TDIM * GDIM];    // hoisted input-gate preacts (1 GiB)
static __device__ float g_seqA[(size_t)BDIM * TDIM * HDIM];  // layer activations ping (256 MB)
static __device__ float g_seqB[(size_t)BDIM * TDIM * HDIM];  // layer activations pong (256 MB)
static __device__ float g_zero[BH];                          // never written -> stays 0
static __device__ float g_hbuf[2 * 3 * BH];                  // decoder h ping-pong; [0] = enc hT
static __device__ float g_cT[3 * BH];                        // encoder final c per layer
static __device__ float g_xfeed[BDIM];                       // decoder scalar feedback
static __device__ unsigned g_count = 0;                      // grid barrier
static __device__ unsigned g_gen = 0;

// ---------------- software grid barrier (all NBLK blocks resident) ----------------
__device__ __forceinline__ void gsync() {
    __syncthreads();
    if (threadIdx.x == 0) {
        unsigned gen = *((volatile unsigned*)&g_gen);
        __threadfence();
        if (atomicAdd(&g_count, 1u) == gridDim.x - 1) {
            atomicExch(&g_count, 0u);
            __threadfence();
            *((volatile unsigned*)&g_gen) = gen + 1u;
        } else {
            while (*((volatile unsigned*)&g_gen) == gen) __nanosleep(64);
        }
        __threadfence();
    }
    __syncthreads();
}

__device__ __forceinline__ float sigm(float x) { return 1.f / (1.f + expf(-x)); }

// Packed fp32x2 FMA (Blackwell FFMA2): d.lo += a.lo*b.lo ; d.hi += a.hi*b.hi
__device__ __forceinline__ void ffma2(unsigned long long& d,
                                      unsigned long long a, unsigned long long b) {
    asm("fma.rn.f32x2 %0, %1, %2, %0;" : "+l"(d) : "l"(a), "l"(b));
}
// Collapse even/odd partial sums.
__device__ __forceinline__ float fsum2(unsigned long long v) {
    float lo, hi;
    asm("mov.b64 {%0, %1}, %2;" : "=f"(lo), "=f"(hi) : "l"(v));
    return lo + hi;
}

// ---------------- tile accumulator over a 512-wide K slice ----------------
// Adds A[128, kbase:kbase+512] @ W[:, kbase:kbase+512]^T (32 selected rows) into acc.
// acc[i][j] is an f32x2 pair of partial sums (even k, odd k).
// Per K-group: 256 threads; tx = t8&7 (unit), ty = t8>>3 (batch group of 4).
__device__ __forceinline__ void accum_K2(
    const float* __restrict__ A, size_t strideA,
    const float* __restrict__ W, int u0, int kbase,
    unsigned long long acc[4][4],
    float (*shA)[36], float (*shW)[36], int t8)
{
    const int ty  = t8 >> 3;
    const int tx  = t8 & 7;
    const int kqo = tx * 4;            // k-offset within 32-chunk (float4 granularity)
    const int b0  = t8 >> 3;           // 0..31: A row group base / W row id

    const int wrow = ((b0 & 3) << 10) + u0 + (b0 >> 2);  // gate (b0&3), unit (b0>>2)
    const float* Wp = W + (size_t)wrow * HDIM + kbase + kqo;
    const float* Ap = A + kbase + kqo;

    float4 ra[4], rw;
#pragma unroll
    for (int r = 0; r < 4; r++)
        ra[r] = *(const float4*)&Ap[(size_t)(b0 + 32 * r) * strideA];
    rw = *(const float4*)&Wp[0];

#pragma unroll 1
    for (int ch = 0; ch < 16; ch++) {      // 16 chunks x 32 k = 512 K per group
        __syncthreads();
#pragma unroll
        for (int r = 0; r < 4; r++)
            *(float4*)&shA[b0 + 32 * r][kqo] = ra[r];
        *(float4*)&shW[b0][kqo] = rw;
        __syncthreads();
        if (ch < 15) {
            const int k0 = (ch + 1) * 32;
#pragma unroll
            for (int r = 0; r < 4; r++)
                ra[r] = *(const float4*)&Ap[(size_t)(b0 + 32 * r) * strideA + k0];
            rw = *(const float4*)&Wp[k0];
        }
#pragma unroll
        for (int k4 = 0; k4 < 8; k4++) {
            const ulonglong2 a0 = *(const ulonglong2*)&shA[4 * ty + 0][4 * k4];
            const ulonglong2 a1 = *(const ulonglong2*)&shA[4 * ty + 1][4 * k4];
            const ulonglong2 a2 = *(const ulonglong2*)&shA[4 * ty + 2][4 * k4];
            const ulonglong2 a3 = *(const ulonglong2*)&shA[4 * ty + 3][4 * k4];
            const ulonglong2 w0 = *(const ulonglong2*)&shW[4 * tx + 0][4 * k4];
            const ulonglong2 w1 = *(const ulonglong2*)&shW[4 * tx + 1][4 * k4];
            const ulonglong2 w2 = *(const ulonglong2*)&shW[4 * tx + 2][4 * k4];
            const ulonglong2 w3 = *(const ulonglong2*)&shW[4 * tx + 3][4 * k4];
            ffma2(acc[0][0], a0.x, w0.x); ffma2(acc[0][0], a0.y, w0.y);
            ffma2(acc[0][1], a0.x, w1.x); ffma2(acc[0][1], a0.y, w1.y);
            ffma2(acc[0][2], a0.x, w2.x); ffma2(acc[0][2], a0.y, w2.y);
            ffma2(acc[0][3], a0.x, w3.x); ffma2(acc[0][3], a0.y, w3.y);
            ffma2(acc[1][0], a1.x, w0.x); ffma2(acc[1][0], a1.y, w0.y);
            ffma2(acc[1][1], a1.x, w1.x); ffma2(acc[1][1], a1.y, w1.y);
            ffma2(acc[1][2], a1.x, w2.x); ffma2(acc[1][2], a1.y, w2.y);
            ffma2(acc[1][3], a1.x, w3.x); ffma2(acc[1][3], a1.y, w3.y);
            ffma2(acc[2][0], a2.x, w0.x); ffma2(acc[2][0], a2.y, w0.y);
            ffma2(acc[2][1], a2.x, w1.x); ffma2(acc[2][1], a2.y, w1.y);
            ffma2(acc[2][2], a2.x, w2.x); ffma2(acc[2][2], a2.y, w2.y);
            ffma2(acc[2][3], a2.x, w3.x); ffma2(acc[2][3], a2.y, w3.y);
            ffma2(acc[3][0], a3.x, w0.x); ffma2(acc[3][0], a3.y, w0.y);
            ffma2(acc[3][1], a3.x, w1.x); ffma2(acc[3][1], a3.y, w1.y);
            ffma2(acc[3][2], a3.x, w2.x); ffma2(acc[3][2], a3.y, w2.y);
            ffma2(acc[3][3], a3.x, w3.x); ffma2(acc[3][3], a3.y, w3.y);
        }
    }
}

// Collapse f32x2 partials and reduce across the 2 K-groups through smem.
// Returns true partial sums in fa for kg0 threads; kg1's fa is consumed.
__device__ __forceinline__ void reduce_kg(
    unsigned long long acc[4][4], float fa[4][4],
    float* red, int kg, int t8)
{
#pragma unroll
    for (int i = 0; i < 4; i++)
#pragma unroll
        for (int j = 0; j < 4; j++) fa[i][j] = fsum2(acc[i][j]);
    __syncthreads();
    if (kg) {
#pragma unroll
        for (int i = 0; i < 4; i++)
#pragma unroll
            for (int j = 0; j < 4; j++) red[t8 * 16 + i * 4 + j] = fa[i][j];
    }
    __syncthreads();
    if (!kg) {
#pragma unroll
        for (int i = 0; i < 4; i++)
#pragma unroll
            for (int j = 0; j < 4; j++) fa[i][j] += red[t8 * 16 + i * 4 + j];
    }
}

// ---------------- persistent encoder layer ----------------
__global__ void __launch_bounds__(NTHR, 1) enc_layer_kernel(
    const float* __restrict__ Whh, const float* __restrict__ xg,
    const float* __restrict__ bih, const float* __restrict__ bhh,
    const float* __restrict__ zbuf,
    float* __restrict__ seq_out,     // [B,T,H]
    float* __restrict__ cT_out, float* __restrict__ hT_out)
{
    __shared__ float shA[2][128][36];
    __shared__ float shW[2][32][36];
    float* red = &shA[1][0][0];      // 4096 floats, reused after kg1's compute

    const int tid = threadIdx.x;
    const int kg  = tid >> 8;        // K-group 0/1
    const int t8  = tid & 255;
    const int tx = t8 & 7, ty = t8 >> 3;
    const int u0 = blockIdx.x * 8;
    const int u  = u0 + tx;

    float bs[4];
#pragma unroll
    for (int q = 0; q < 4; q++) bs[q] = bih[(q << 10) + u] + bhh[(q << 10) + u];

    float cl[4] = {0.f, 0.f, 0.f, 0.f};
    float hl[4] = {0.f, 0.f, 0.f, 0.f};

#pragma unroll 1
    for (int t = 0; t < TDIM; t++) {
        unsigned long long acc[4][4];
#pragma unroll
        for (int i = 0; i < 4; i++)
#pragma unroll
            for (int j = 0; j < 4; j++) acc[i][j] = 0ull;

        const float* Ap = t ? (seq_out + (size_t)(t - 1) * HDIM) : zbuf;
        const size_t st = t ? (size_t)TDIM * HDIM : (size_t)HDIM;
        accum_K2(Ap, st, Whh, u0, kg * 512, acc, shA[kg], shW[kg], t8);

        float fa[4][4];
        reduce_kg(acc, fa, red, kg, t8);

        if (!kg) {
#pragma unroll
            for (int i = 0; i < 4; i++) {
                const int b = 4 * ty + i;
                const size_t xr = ((size_t)b * TDIM + t) * GDIM;
                float ip = fa[i][0] + xg[xr + u]        + bs[0];
                float fp = fa[i][1] + xg[xr + 1024 + u] + bs[1];
                float gp = fa[i][2] + xg[xr + 2048 + u] + bs[2];
                float op = fa[i][3] + xg[xr + 3072 + u] + bs[3];
                float cn = sigm(fp) * cl[i] + sigm(ip) * tanhf(gp);
                float hn = sigm(op) * tanhf(cn);
                cl[i] = cn; hl[i] = hn;
                seq_out[((size_t)b * TDIM + t) * HDIM + u] = hn;
            }
        }
        gsync();
    }
    if (!kg) {
#pragma unroll
        for (int i = 0; i < 4; i++) {
            const int b = 4 * ty + i;
            cT_out[b * HDIM + u] = cl[i];
            hT_out[b * HDIM + u] = hl[i];
        }
    }
}

// ---------------- persistent decoder (all 3 layers + head + feedback) ----------------
__global__ void __launch_bounds__(NTHR, 1) dec_kernel(
    const float* __restrict__ dWih0, const float* __restrict__ dWhh0,
    const float* __restrict__ dbih0, const float* __restrict__ dbhh0,
    const float* __restrict__ dWih,  const float* __restrict__ dWhh,
    const float* __restrict__ dbih,  const float* __restrict__ dbhh,
    const float* __restrict__ Wu,    const float* __restrict__ bu,
    const float* __restrict__ y,     const int* __restrict__ force,
    float* __restrict__ hbuf, const float* __restrict__ cinit,
    float* __restrict__ xfeed, float* __restrict__ out)
{
    __shared__ float shA[2][128][36];
    __shared__ float shW[2][32][36];
    __shared__ float red2[16];
    float* red = &shA[1][0][0];

    const int tid = threadIdx.x;
    const int kg  = tid >> 8;
    const int t8  = tid & 255;
    const int tx = t8 & 7, ty = t8 >> 3;
    const int u0 = blockIdx.x * 8;
    const int u  = u0 + tx;

    float bs0[4], bs1[4], bs2[4], wc0[4];
#pragma unroll
    for (int q = 0; q < 4; q++) {
        const int g = (q << 10) + u;
        bs0[q] = dbih0[g] + dbhh0[g];
        bs1[q] = dbih[g] + dbhh[g];
        bs2[q] = dbih[GDIM + g] + dbhh[GDIM + g];
        wc0[q] = dWih0[g];
    }
    float c0[4], c1[4], c2[4];
#pragma unroll
    for (int i = 0; i < 4; i++) {
        const int b = 4 * ty + i;
        c0[i] = cinit[0 * BH + b * HDIM + u];
        c1[i] = cinit[1 * BH + b * HDIM + u];
        c2[i] = cinit[2 * BH + b * HDIM + u];
    }
    if (blockIdx.x == 0 && tid < BDIM) {
        xfeed[tid] = y[(size_t)tid * TDIM];
        out[(size_t)tid * TDIM] = 0.f;       // output[:,0] = 0
    }
    gsync();

#pragma unroll 1
    for (int s = 0; s < TDIM - 1; s++) {
        const int p = s & 1;
        float* hb_r = hbuf + (size_t)p * 3 * BH;
        float* hb_w = hbuf + (size_t)(p ^ 1) * 3 * BH;
        unsigned long long acc[4][4];
        float fa[4][4];

        // ----- layer 0: gates = h0 @ Whh0^T + xfeed*Wih0 + b -----
#pragma unroll
        for (int i = 0; i < 4; i++)
#pragma unroll
            for (int j = 0; j < 4; j++) acc[i][j] = 0ull;
        accum_K2(hb_r, HDIM, dWhh0, u0, kg * 512, acc, shA[kg], shW[kg], t8);
        reduce_kg(acc, fa, red, kg, t8);
        if (!kg) {
            float xf[4];
#pragma unroll
            for (int i = 0; i < 4; i++) xf[i] = xfeed[4 * ty + i];
#pragma unroll
            for (int i = 0; i < 4; i++) {
                const int b = 4 * ty + i;
                float ip = fa[i][0] + xf[i] * wc0[0] + bs0[0];
                float fp = fa[i][1] + xf[i] * wc0[1] + bs0[1];
                float gp = fa[i][2] + xf[i] * wc0[2] + bs0[2];
                float op = fa[i][3] + xf[i] * wc0[3] + bs0[3];
                float cn = sigm(fp) * c0[i] + sigm(ip) * tanhf(gp);
                float hn = sigm(op) * tanhf(cn);
                c0[i] = cn;
                hb_w[b * HDIM + u] = hn;
            }
        }
        gsync();

        // ----- layer 1: gates = h0_new @ Wih1^T + h1 @ Whh1^T + b -----
#pragma unroll
        for (int i = 0; i < 4; i++)
#pragma unroll
            for (int j = 0; j < 4; j++) acc[i][j] = 0ull;
        accum_K2(hb_w, HDIM, dWih, u0, kg * 512, acc, shA[kg], shW[kg], t8);
        accum_K2(hb_r + BH, HDIM, dWhh, u0, kg * 512, acc, shA[kg], shW[kg], t8);
        reduce_kg(acc, fa, red, kg, t8);
        if (!kg) {
#pragma unroll
            for (int i = 0; i < 4; i++) {
                const int b = 4 * ty + i;
                float ip = fa[i][0] + bs1[0];
                float fp = fa[i][1] + bs1[1];
                float gp = fa[i][2] + bs1[2];
                float op = fa[i][3] + bs1[3];
                float cn = sigm(fp) * c1[i] + sigm(ip) * tanhf(gp);
                float hn = sigm(op) * tanhf(cn);
                c1[i] = cn;
                hb_w[BH + b * HDIM + u] = hn;
            }
        }
        gsync();

        // ----- layer 2 -----
#pragma unroll
        for (int i = 0; i < 4; i++)
#pragma unroll
            for (int j = 0; j < 4; j++) acc[i][j] = 0ull;
        accum_K2(hb_w + BH, HDIM, dWih + (size_t)GDIM * HDIM, u0, kg * 512,
                 acc, shA[kg], shW[kg], t8);
        accum_K2(hb_r + 2 * BH, HDIM, dWhh + (size_t)GDIM * HDIM, u0, kg * 512,
                 acc, shA[kg], shW[kg], t8);
        reduce_kg(acc, fa, red, kg, t8);
        if (!kg) {
#pragma unroll
            for (int i = 0; i < 4; i++) {
                const int b = 4 * ty + i;
                float ip = fa[i][0] + bs2[0];
                float fp = fa[i][1] + bs2[1];
                float gp = fa[i][2] + bs2[2];
                float op = fa[i][3] + bs2[3];
                float cn = sigm(fp) * c2[i] + sigm(ip) * tanhf(gp);
                float hn = sigm(op) * tanhf(cn);
                c2[i] = cn;
                hb_w[2 * BH + b * HDIM + u] = hn;
            }
        }
        gsync();

        // ----- output head + teacher forcing: block b handles batch row b -----
        {
            const float* hr = hb_w + 2 * BH + (size_t)blockIdx.x * HDIM;
            float a = 0.f;
#pragma unroll 2
            for (int k = tid; k < HDIM; k += NTHR) a += hr[k] * Wu[k];
#pragma unroll
            for (int o = 16; o; o >>= 1) a += __shfl_xor_sync(0xFFFFFFFFu, a, o);
            if ((tid & 31) == 0) red2[tid >> 5] = a;
            __syncthreads();
            if (tid == 0) {
                float ov = bu[0];
#pragma unroll
                for (int w = 0; w < 16; w++) ov += red2[w];
                out[(size_t)blockIdx.x * TDIM + s + 1] = ov;
                xfeed[blockIdx.x] = (force[s] > 0) ? y[(size_t)blockIdx.x * TDIM + s + 1] : ov;
            }
        }
        gsync();
    }
}

// ---------------- full-grid NT GEMM for the hoisted input projections ----------------
// C[M,N] = A@B^T ; A row-major [M,K], B row-major [N,K]; M%64==0, N%64==0, K%16==0.
__global__ void __launch_bounds__(256) gemm_hoist(
    const float* __restrict__ A, const float* __restrict__ B, int K,
    float* __restrict__ C, int M, int N)
{
    __shared__ float As[16][68];
    __shared__ float Bs[16][68];
    const int tid = threadIdx.x;
    const int tx = tid & 15, ty = tid >> 4;
    const int m0 = blockIdx.y * 64, n0 = blockIdx.x * 64;
    const int lr = tid >> 2;
    const int lc = (tid & 3) * 4;

    float acc[4][4];
#pragma unroll
    for (int i = 0; i < 4; i++)
#pragma unroll
        for (int j = 0; j < 4; j++) acc[i][j] = 0.f;

#pragma unroll 1
    for (int k0 = 0; k0 < K; k0 += 16) {
        float4 av = *(const float4*)&A[(size_t)(m0 + lr) * K + k0 + lc];
        float4 bv = *(const float4*)&B[(size_t)(n0 + lr) * K + k0 + lc];
        __syncthreads();
        As[lc + 0][lr] = av.x; As[lc + 1][lr] = av.y; As[lc + 2][lr] = av.z; As[lc + 3][lr] = av.w;
        Bs[lc + 0][lr] = bv.x; Bs[lc + 1][lr] = bv.y; Bs[lc + 2][lr] = bv.z; Bs[lc + 3][lr] = bv.w;
        __syncthreads();
#pragma unroll
        for (int k = 0; k < 16; k++) {
            float4 a = *(const float4*)&As[k][ty * 4];
            float4 b = *(const float4*)&Bs[k][tx * 4];
            acc[0][0] += a.x * b.x; acc[0][1] += a.x * b.y; acc[0][2] += a.x * b.z; acc[0][3] += a.x * b.w;
            acc[1][0] += a.y * b.x; acc[1][1] += a.y * b.y; acc[1][2] += a.y * b.z; acc[1][3] += a.y * b.w;
            acc[2][0] += a.z * b.x; acc[2][1] += a.z * b.y; acc[2][2] += a.z * b.z; acc[2][3] += a.z * b.w;
            acc[3][0] += a.w * b.x; acc[3][1] += a.w * b.y; acc[3][2] += a.w * b.z; acc[3][3] += a.w * b.w;
        }
    }
#pragma unroll
    for (int i = 0; i < 4; i++) {
        float4 v = make_float4(acc[i][0], acc[i][1], acc[i][2], acc[i][3]);
        *(float4*)&C[(size_t)(m0 + ty * 4 + i) * N + n0 + tx * 4] = v;
    }
}

// ---------------- host orchestration: 7 graph nodes total ----------------
extern "C" void kernel_launch(void* const* d_in, const int* in_sizes, int n_in,
                              void* d_out, int out_size)
{
    (void)in_sizes; (void)n_in; (void)out_size;

    const float* x     = (const float*)d_in[0];
    const float* y     = (const float*)d_in[1];
    const int*   force = (const int*)  d_in[2];
    const float* eWih0 = (const float*)d_in[3];
    const float* eWhh0 = (const float*)d_in[4];
    const float* ebih0 = (const float*)d_in[5];
    const float* ebhh0 = (const float*)d_in[6];
    const float* eWih  = (const float*)d_in[7];
    const float* eWhh  = (const float*)d_in[8];
    const float* ebih  = (const float*)d_in[9];
    const float* ebhh  = (const float*)d_in[10];
    const float* dWih0 = (const float*)d_in[11];
    const float* dWhh0 = (const float*)d_in[12];
    const float* dbih0 = (const float*)d_in[13];
    const float* dbhh0 = (const float*)d_in[14];
    const float* dWih  = (const float*)d_in[15];
    const float* dWhh  = (const float*)d_in[16];
    const float* dbih  = (const float*)d_in[17];
    const float* dbhh  = (const float*)d_in[18];
    const float* Wu    = (const float*)d_in[19];
    const float* bu    = (const float*)d_in[20];
    float* out = (float*)d_out;

    float *xg, *seqA, *seqB, *zero, *hbuf, *cT, *xfeed;
    cudaGetSymbolAddress((void**)&xg,    g_xg);
    cudaGetSymbolAddress((void**)&seqA,  g_seqA);
    cudaGetSymbolAddress((void**)&seqB,  g_seqB);
    cudaGetSymbolAddress((void**)&zero,  g_zero);
    cudaGetSymbolAddress((void**)&hbuf,  g_hbuf);
    cudaGetSymbolAddress((void**)&cT,    g_cT);
    cudaGetSymbolAddress((void**)&xfeed, g_xfeed);

    const dim3 gBig(GDIM / 64, (BDIM * TDIM) / 64);
    const size_t WSTRIDE = (size_t)GDIM * HDIM;

    // encoder layer 0
    gemm_hoist<<<gBig, 256>>>(x, eWih0, IDIM, xg, BDIM * TDIM, GDIM);
    enc_layer_kernel<<<NBLK, NTHR>>>(eWhh0, xg, ebih0, ebhh0, zero,
                                     seqB, cT + 0 * BH, hbuf + 0 * BH);
    // encoder layer 1
    gemm_hoist<<<gBig, 256>>>(seqB, eWih, HDIM, xg, BDIM * TDIM, GDIM);
    enc_layer_kernel<<<NBLK, NTHR>>>(eWhh, xg, ebih, ebhh, zero,
                                     seqA, cT + 1 * BH, hbuf + 1 * BH);
    // encoder layer 2
    gemm_hoist<<<gBig, 256>>>(seqA, eWih + WSTRIDE, HDIM, xg, BDIM * TDIM, GDIM);
    enc_layer_kernel<<<NBLK, NTHR>>>(eWhh + WSTRIDE, xg, ebih + GDIM, ebhh + GDIM, zero,
                                     seqB, cT + 2 * BH, hbuf + 2 * BH);
    // decoder (persistent, all 511 steps)
    dec_kernel<<<NBLK, NTHR>>>(dWih0, dWhh0, dbih0, dbhh0,
                               dWih, dWhh, dbih, dbhh,
                               Wu, bu, y, force,
                               hbuf, cT, xfeed, out);
}

// round 11
// speedup vs baseline: 4.7572x; 4.7572x over previous
#include <cuda_runtime.h>
#include <cuda_bf16.h>
#include <math.h>
#include <stdint.h>
#include <stddef.h>

#define BDIM 128
#define TDIM 512
#define IDIM 32
#define HDIM 1024
#define GDIM 4096
#define BH   (BDIM*HDIM)
#define NBLK 128
#define NTHR 256
#define MSZ  4194304   // 4096*1024 elements per weight matrix

// weight slots in the bf16 tiled store
#define W_EWH0 0
#define W_EWH1 1
#define W_EWH2 2
#define W_DWH0 3
#define W_DWI1 4
#define W_DWI2 5
#define W_DWH1 6
#define W_DWH2 7

// ---------------- static device scratch (no allocations anywhere) ----------------
static __device__ __nv_bfloat16 g_whi[(size_t)8 * MSZ];      // weights hi, tiled
static __device__ __nv_bfloat16 g_wlo[(size_t)8 * MSZ];      // weights lo, tiled
static __device__ __nv_bfloat16 g_eh16[2][2][BH];            // encoder h ping-pong [par][hi/lo], tiled
static __device__ __nv_bfloat16 g_zero16[BH];                // never written -> zeros
static __device__ __nv_bfloat16 g_dh16[2][3][2][BH];         // decoder h [par][layer][hi/lo], tiled
static __device__ float g_h2f[BH];                           // decoder top-layer h fp32 (for head)
static __device__ float g_xg[(size_t)BDIM * TDIM * GDIM];    // hoisted input-gate preacts
static __device__ float g_seqA[(size_t)BDIM * TDIM * HDIM];
static __device__ float g_seqB[(size_t)BDIM * TDIM * HDIM];
static __device__ float g_cT[3 * BH];                        // encoder final c
static __device__ float g_xfeed[BDIM];
static __device__ unsigned g_count = 0;
static __device__ unsigned g_gen = 0;

// ---------------- software grid barrier (all NBLK blocks resident) ----------------
__device__ __forceinline__ void gsync() {
    __syncthreads();
    if (threadIdx.x == 0) {
        unsigned gen = *((volatile unsigned*)&g_gen);
        __threadfence();
        if (atomicAdd(&g_count, 1u) == gridDim.x - 1) {
            atomicExch(&g_count, 0u);
            __threadfence();
            *((volatile unsigned*)&g_gen) = gen + 1u;
        } else {
            while (*((volatile unsigned*)&g_gen) == gen) __nanosleep(64);
        }
        __threadfence();
    }
    __syncthreads();
}

__device__ __forceinline__ float sigm(float x) { return 1.f / (1.f + expf(-x)); }

// tiled index for an element (row, k) of a [4096(rows) x 1024(k)] matrix,
// 8x8 bf16 tiles, tile raster = row-tile-major then k-tile: lane-coalesced frags.
__device__ __forceinline__ uint32_t widx(int row, int k) {
    return (uint32_t)(row >> 3) * 8192u + (uint32_t)(k >> 3) * 64u
         + (uint32_t)(row & 7) * 8u + (uint32_t)(k & 7);
}
// same tiling for H [128(batch=n) x 1024(u=k)]
__device__ __forceinline__ uint32_t hidx(int b, int u) {
    return (uint32_t)(b >> 3) * 8192u + (uint32_t)(u >> 3) * 64u
         + (uint32_t)(b & 7) * 8u + (uint32_t)(u & 7);
}

#define MMA16816(C, A0, A1, A2, A3, B0, B1) \
    asm volatile("mma.sync.aligned.m16n8k16.row.col.f32.bf16.bf16.f32 " \
        "{%0,%1,%2,%3}, {%4,%5,%6,%7}, {%8,%9}, {%0,%1,%2,%3};" \
        : "+f"((C)[0]), "+f"((C)[1]), "+f"((C)[2]), "+f"((C)[3]) \
        : "r"(A0), "r"(A1), "r"(A2), "r"(A3), "r"(B0), "r"(B1))

// ---------------- weight prep: fp32 -> bf16 hi/lo in tiled layout ----------------
__global__ void prep_w(const float* p0, const float* p1, const float* p2, const float* p3,
                       const float* p4, const float* p5, const float* p6, const float* p7)
{
    for (size_t i = (size_t)blockIdx.x * blockDim.x + threadIdx.x;
         i < (size_t)8 * MSZ; i += (size_t)gridDim.x * blockDim.x) {
        int m = (int)(i >> 22);
        int e = (int)(i & (MSZ - 1));
        const float* src;
        switch (m) {
            case 0: src = p0; break; case 1: src = p1; break;
            case 2: src = p2; break; case 3: src = p3; break;
            case 4: src = p4; break; case 5: src = p5; break;
            case 6: src = p6; break; default: src = p7; break;
        }
        float v = src[e];
        __nv_bfloat16 h = __float2bfloat16(v);
        __nv_bfloat16 l = __float2bfloat16(v - __bfloat162float(h));
        int row = e >> 10, k = e & 1023;
        size_t dst = (size_t)m * MSZ + widx(row, k);
        g_whi[dst] = h;
        g_wlo[dst] = l;
    }
}

// ---------------- block MMA: C[32 Wrows, 128 batch] += W @ H^T (3-term bf16) ----------------
// Block owns W rows {gate q, unit u0+j} laid out as r_local = q*8+j.
// Warp w: m-tile = w&1 (16 r_local rows), n-tiles = 4 of 8 at (w>>1)*32.
__device__ __forceinline__ void accum_mma(
    const __nv_bfloat16* __restrict__ Whi, const __nv_bfloat16* __restrict__ Wlo,
    const __nv_bfloat16* __restrict__ Hhi, const __nv_bfloat16* __restrict__ Hlo,
    float C[4][4], int u0)
{
    const int tid = threadIdx.x;
    const int w = tid >> 5, lane = tid & 31;
    const int q0 = (w & 1) * 2;              // gate of a0/a2 rows
    const int q1 = q0 + 1;                   // gate of a1/a3 rows
    const uint32_t lo2 = 2u * (uint32_t)lane;
    const uint32_t wb0 = (uint32_t)(q0 * 128 + (u0 >> 3)) * 8192u + lo2;
    const uint32_t wb1 = (uint32_t)(q1 * 128 + (u0 >> 3)) * 8192u + lo2;
    uint32_t hb[4];
#pragma unroll
    for (int j = 0; j < 4; j++)
        hb[j] = (uint32_t)((w >> 1) * 4 + j) * 8192u + lo2;

#pragma unroll 2
    for (int kt = 0; kt < 128; kt += 2) {
        const uint32_t ko = (uint32_t)kt * 64u;
        uint32_t ah0 = *(const uint32_t*)(Whi + wb0 + ko);
        uint32_t ah1 = *(const uint32_t*)(Whi + wb1 + ko);
        uint32_t ah2 = *(const uint32_t*)(Whi + wb0 + ko + 64);
        uint32_t ah3 = *(const uint32_t*)(Whi + wb1 + ko + 64);
        uint32_t al0 = *(const uint32_t*)(Wlo + wb0 + ko);
        uint32_t al1 = *(const uint32_t*)(Wlo + wb1 + ko);
        uint32_t al2 = *(const uint32_t*)(Wlo + wb0 + ko + 64);
        uint32_t al3 = *(const uint32_t*)(Wlo + wb1 + ko + 64);
#pragma unroll
        for (int j = 0; j < 4; j++) {
            uint32_t bh0 = *(const uint32_t*)(Hhi + hb[j] + ko);
            uint32_t bh1 = *(const uint32_t*)(Hhi + hb[j] + ko + 64);
            uint32_t bl0 = *(const uint32_t*)(Hlo + hb[j] + ko);
            uint32_t bl1 = *(const uint32_t*)(Hlo + hb[j] + ko + 64);
            MMA16816(C[j], ah0, ah1, ah2, ah3, bh0, bh1);  // hi*hi
            MMA16816(C[j], ah0, ah1, ah2, ah3, bl0, bl1);  // hi*lo
            MMA16816(C[j], al0, al1, al2, al3, bh0, bh1);  // lo*hi
        }
    }
}

// store C fragments into gates smem [r_local 32][batch 128]
__device__ __forceinline__ void store_C(float C[4][4], float (*gates_s)[132])
{
    const int tid = threadIdx.x;
    const int w = tid >> 5, lane = tid & 31;
    const int g = lane >> 2, tg = lane & 3;
    const int r0 = (w & 1) * 16 + g;
    const int r1 = r0 + 8;
#pragma unroll
    for (int j = 0; j < 4; j++) {
        const int cb = (w >> 1) * 32 + j * 8 + 2 * tg;
        gates_s[r0][cb]     = C[j][0];
        gates_s[r0][cb + 1] = C[j][1];
        gates_s[r1][cb]     = C[j][2];
        gates_s[r1][cb + 1] = C[j][3];
    }
}

// ---------------- persistent encoder layer ----------------
__global__ void __launch_bounds__(NTHR, 1) enc_layer_kernel(
    int wslot, int dslot,
    const float* __restrict__ bih, const float* __restrict__ bhh,
    float* __restrict__ seq_out)
{
    __shared__ float gates_s[32][132];
    const int tid = threadIdx.x;
    const int u0 = blockIdx.x * 8;
    const int j = tid >> 5, bl = tid & 31;
    const int u = u0 + j;
    const __nv_bfloat16* Whi = g_whi + (size_t)wslot * MSZ;
    const __nv_bfloat16* Wlo = g_wlo + (size_t)wslot * MSZ;

    float bs[4];
#pragma unroll
    for (int q = 0; q < 4; q++) bs[q] = bih[(q << 10) + u] + bhh[(q << 10) + u];

    float cl[4] = {0.f, 0.f, 0.f, 0.f};
    float hl[4] = {0.f, 0.f, 0.f, 0.f};

#pragma unroll 1
    for (int t = 0; t < TDIM; t++) {
        float C[4][4];
#pragma unroll
        for (int a = 0; a < 4; a++)
#pragma unroll
            for (int b = 0; b < 4; b++) C[a][b] = 0.f;

        const __nv_bfloat16* Hhi = t ? &g_eh16[t & 1][0][0] : g_zero16;
        const __nv_bfloat16* Hlo = t ? &g_eh16[t & 1][1][0] : g_zero16;
        accum_mma(Whi, Wlo, Hhi, Hlo, C, u0);
        store_C(C, gates_s);
        __syncthreads();

        const int wp = (t + 1) & 1;
#pragma unroll
        for (int i = 0; i < 4; i++) {
            const int b = bl + 32 * i;
            const size_t xr = ((size_t)b * TDIM + t) * GDIM;
            float ip = gates_s[j][b]      + g_xg[xr + u]        + bs[0];
            float fp = gates_s[8 + j][b]  + g_xg[xr + 1024 + u] + bs[1];
            float gp = gates_s[16 + j][b] + g_xg[xr + 2048 + u] + bs[2];
            float op = gates_s[24 + j][b] + g_xg[xr + 3072 + u] + bs[3];
            float cn = sigm(fp) * cl[i] + sigm(ip) * tanhf(gp);
            float hn = sigm(op) * tanhf(cn);
            cl[i] = cn; hl[i] = hn;
            seq_out[((size_t)b * TDIM + t) * HDIM + u] = hn;
            __nv_bfloat16 hh = __float2bfloat16(hn);
            __nv_bfloat16 hlo = __float2bfloat16(hn - __bfloat162float(hh));
            const uint32_t hd = hidx(b, u);
            g_eh16[wp][0][hd] = hh;
            g_eh16[wp][1][hd] = hlo;
        }
        gsync();
    }
    // export final states for the decoder
#pragma unroll
    for (int i = 0; i < 4; i++) {
        const int b = bl + 32 * i;
        g_cT[dslot * BH + b * HDIM + u] = cl[i];
        __nv_bfloat16 hh = __float2bfloat16(hl[i]);
        __nv_bfloat16 hlo = __float2bfloat16(hl[i] - __bfloat162float(hh));
        const uint32_t hd = hidx(b, u);
        g_dh16[0][dslot][0][hd] = hh;
        g_dh16[0][dslot][1][hd] = hlo;
    }
}

// ---------------- persistent decoder ----------------
__global__ void __launch_bounds__(NTHR, 1) dec_kernel(
    const float* __restrict__ dWih0,
    const float* __restrict__ dbih0, const float* __restrict__ dbhh0,
    const float* __restrict__ dbih,  const float* __restrict__ dbhh,
    const float* __restrict__ Wu,    const float* __restrict__ bu,
    const float* __restrict__ y,     const int* __restrict__ force,
    float* __restrict__ out)
{
    __shared__ float gates_s[32][132];
    __shared__ float red2[8];
    const int tid = threadIdx.x;
    const int u0 = blockIdx.x * 8;
    const int j = tid >> 5, bl = tid & 31;
    const int u = u0 + j;

    float bs0[4], bs1[4], bs2[4], wc0[4];
#pragma unroll
    for (int q = 0; q < 4; q++) {
        const int g = (q << 10) + u;
        bs0[q] = dbih0[g] + dbhh0[g];
        bs1[q] = dbih[g] + dbhh[g];
        bs2[q] = dbih[GDIM + g] + dbhh[GDIM + g];
        wc0[q] = dWih0[g];
    }
    float c0[4], c1[4], c2[4];
#pragma unroll
    for (int i = 0; i < 4; i++) {
        const int b = bl + 32 * i;
        c0[i] = g_cT[0 * BH + b * HDIM + u];
        c1[i] = g_cT[1 * BH + b * HDIM + u];
        c2[i] = g_cT[2 * BH + b * HDIM + u];
    }
    if (blockIdx.x == 0 && tid < BDIM) {
        g_xfeed[tid] = y[(size_t)tid * TDIM];
        out[(size_t)tid * TDIM] = 0.f;     // output[:,0] = 0
    }
    gsync();

#pragma unroll 1
    for (int s = 0; s < TDIM - 1; s++) {
        const int p = s & 1;
        float C[4][4];

        // ----- layer 0: gates = h0 @ Whh0^T (+ xfeed*Wih0 + b) -----
#pragma unroll
        for (int a = 0; a < 4; a++)
#pragma unroll
            for (int b = 0; b < 4; b++) C[a][b] = 0.f;
        accum_mma(g_whi + (size_t)W_DWH0 * MSZ, g_wlo + (size_t)W_DWH0 * MSZ,
                  &g_dh16[p][0][0][0], &g_dh16[p][0][1][0], C, u0);
        store_C(C, gates_s);
        __syncthreads();
#pragma unroll
        for (int i = 0; i < 4; i++) {
            const int b = bl + 32 * i;
            const float xf = g_xfeed[b];
            float ip = gates_s[j][b]      + xf * wc0[0] + bs0[0];
            float fp = gates_s[8 + j][b]  + xf * wc0[1] + bs0[1];
            float gp = gates_s[16 + j][b] + xf * wc0[2] + bs0[2];
            float op = gates_s[24 + j][b] + xf * wc0[3] + bs0[3];
            float cn = sigm(fp) * c0[i] + sigm(ip) * tanhf(gp);
            float hn = sigm(op) * tanhf(cn);
            c0[i] = cn;
            __nv_bfloat16 hh = __float2bfloat16(hn);
            __nv_bfloat16 hlo = __float2bfloat16(hn - __bfloat162float(hh));
            const uint32_t hd = hidx(b, u);
            g_dh16[p ^ 1][0][0][hd] = hh;
            g_dh16[p ^ 1][0][1][hd] = hlo;
        }
        gsync();

        // ----- layer 1: gates = h0_new @ Wih1^T + h1 @ Whh1^T -----
#pragma unroll
        for (int a = 0; a < 4; a++)
#pragma unroll
            for (int b = 0; b < 4; b++) C[a][b] = 0.f;
        accum_mma(g_whi + (size_t)W_DWI1 * MSZ, g_wlo + (size_t)W_DWI1 * MSZ,
                  &g_dh16[p ^ 1][0][0][0], &g_dh16[p ^ 1][0][1][0], C, u0);
        accum_mma(g_whi + (size_t)W_DWH1 * MSZ, g_wlo + (size_t)W_DWH1 * MSZ,
                  &g_dh16[p][1][0][0], &g_dh16[p][1][1][0], C, u0);
        store_C(C, gates_s);
        __syncthreads();
#pragma unroll
        for (int i = 0; i < 4; i++) {
            const int b = bl + 32 * i;
            float ip = gates_s[j][b]      + bs1[0];
            float fp = gates_s[8 + j][b]  + bs1[1];
            float gp = gates_s[16 + j][b] + bs1[2];
            float op = gates_s[24 + j][b] + bs1[3];
            float cn = sigm(fp) * c1[i] + sigm(ip) * tanhf(gp);
            float hn = sigm(op) * tanhf(cn);
            c1[i] = cn;
            __nv_bfloat16 hh = __float2bfloat16(hn);
            __nv_bfloat16 hlo = __float2bfloat16(hn - __bfloat162float(hh));
            const uint32_t hd = hidx(b, u);
            g_dh16[p ^ 1][1][0][hd] = hh;
            g_dh16[p ^ 1][1][1][hd] = hlo;
        }
        gsync();

        // ----- layer 2 -----
#pragma unroll
        for (int a = 0; a < 4; a++)
#pragma unroll
            for (int b = 0; b < 4; b++) C[a][b] = 0.f;
        accum_mma(g_whi + (size_t)W_DWI2 * MSZ, g_wlo + (size_t)W_DWI2 * MSZ,
                  &g_dh16[p ^ 1][1][0][0], &g_dh16[p ^ 1][1][1][0], C, u0);
        accum_mma(g_whi + (size_t)W_DWH2 * MSZ, g_wlo + (size_t)W_DWH2 * MSZ,
                  &g_dh16[p][2][0][0], &g_dh16[p][2][1][0], C, u0);
        store_C(C, gates_s);
        __syncthreads();
#pragma unroll
        for (int i = 0; i < 4; i++) {
            const int b = bl + 32 * i;
            float ip = gates_s[j][b]      + bs2[0];
            float fp = gates_s[8 + j][b]  + bs2[1];
            float gp = gates_s[16 + j][b] + bs2[2];
            float op = gates_s[24 + j][b] + bs2[3];
            float cn = sigm(fp) * c2[i] + sigm(ip) * tanhf(gp);
            float hn = sigm(op) * tanhf(cn);
            c2[i] = cn;
            g_h2f[b * HDIM + u] = hn;
            __nv_bfloat16 hh = __float2bfloat16(hn);
            __nv_bfloat16 hlo = __float2bfloat16(hn - __bfloat162float(hh));
            const uint32_t hd = hidx(b, u);
            g_dh16[p ^ 1][2][0][hd] = hh;
            g_dh16[p ^ 1][2][1][hd] = hlo;
        }
        gsync();

        // ----- output head + teacher forcing: block b handles batch row b -----
        {
            const float* hr = g_h2f + (size_t)blockIdx.x * HDIM;
            float a = 0.f;
#pragma unroll 4
            for (int k = tid; k < HDIM; k += NTHR) a += hr[k] * Wu[k];
#pragma unroll
            for (int o = 16; o; o >>= 1) a += __shfl_xor_sync(0xFFFFFFFFu, a, o);
            if ((tid & 31) == 0) red2[tid >> 5] = a;
            __syncthreads();
            if (tid == 0) {
                float ov = bu[0];
#pragma unroll
                for (int ww = 0; ww < 8; ww++) ov += red2[ww];
                out[(size_t)blockIdx.x * TDIM + s + 1] = ov;
                g_xfeed[blockIdx.x] = (force[s] > 0) ? y[(size_t)blockIdx.x * TDIM + s + 1] : ov;
            }
        }
        gsync();
    }
}

// ---------------- full-grid fp32 NT GEMM for the hoisted input projections ----------------
__global__ void __launch_bounds__(256) gemm_hoist(
    const float* __restrict__ A, const float* __restrict__ B, int K,
    float* __restrict__ C, int M, int N)
{
    __shared__ float As[16][68];
    __shared__ float Bs[16][68];
    const int tid = threadIdx.x;
    const int tx = tid & 15, ty = tid >> 4;
    const int m0 = blockIdx.y * 64, n0 = blockIdx.x * 64;
    const int lr = tid >> 2;
    const int lc = (tid & 3) * 4;

    float acc[4][4];
#pragma unroll
    for (int i = 0; i < 4; i++)
#pragma unroll
        for (int jj = 0; jj < 4; jj++) acc[i][jj] = 0.f;

#pragma unroll 1
    for (int k0 = 0; k0 < K; k0 += 16) {
        float4 av = *(const float4*)&A[(size_t)(m0 + lr) * K + k0 + lc];
        float4 bv = *(const float4*)&B[(size_t)(n0 + lr) * K + k0 + lc];
        __syncthreads();
        As[lc + 0][lr] = av.x; As[lc + 1][lr] = av.y; As[lc + 2][lr] = av.z; As[lc + 3][lr] = av.w;
        Bs[lc + 0][lr] = bv.x; Bs[lc + 1][lr] = bv.y; Bs[lc + 2][lr] = bv.z; Bs[lc + 3][lr] = bv.w;
        __syncthreads();
#pragma unroll
        for (int k = 0; k < 16; k++) {
            float4 a = *(const float4*)&As[k][ty * 4];
            float4 b = *(const float4*)&Bs[k][tx * 4];
            acc[0][0] += a.x * b.x; acc[0][1] += a.x * b.y; acc[0][2] += a.x * b.z; acc[0][3] += a.x * b.w;
            acc[1][0] += a.y * b.x; acc[1][1] += a.y * b.y; acc[1][2] += a.y * b.z; acc[1][3] += a.y * b.w;
            acc[2][0] += a.z * b.x; acc[2][1] += a.z * b.y; acc[2][2] += a.z * b.z; acc[2][3] += a.z * b.w;
            acc[3][0] += a.w * b.x; acc[3][1] += a.w * b.y; acc[3][2] += a.w * b.z; acc[3][3] += a.w * b.w;
        }
    }
#pragma unroll
    for (int i = 0; i < 4; i++) {
        float4 v = make_float4(acc[i][0], acc[i][1], acc[i][2], acc[i][3]);
        *(float4*)&C[(size_t)(m0 + ty * 4 + i) * N + n0 + tx * 4] = v;
    }
}

// ---------------- host orchestration: 8 graph nodes ----------------
extern "C" void kernel_launch(void* const* d_in, const int* in_sizes, int n_in,
                              void* d_out, int out_size)
{
    (void)in_sizes; (void)n_in; (void)out_size;

    const float* x     = (const float*)d_in[0];
    const float* y     = (const float*)d_in[1];
    const int*   force = (const int*)  d_in[2];
    const float* eWih0 = (const float*)d_in[3];
    const float* eWhh0 = (const float*)d_in[4];
    const float* ebih0 = (const float*)d_in[5];
    const float* ebhh0 = (const float*)d_in[6];
    const float* eWih  = (const float*)d_in[7];
    const float* eWhh  = (const float*)d_in[8];
    const float* ebih  = (const float*)d_in[9];
    const float* ebhh  = (const float*)d_in[10];
    const float* dWih0 = (const float*)d_in[11];
    const float* dWhh0 = (const float*)d_in[12];
    const float* dbih0 = (const float*)d_in[13];
    const float* dbhh0 = (const float*)d_in[14];
    const float* dWih  = (const float*)d_in[15];
    const float* dWhh  = (const float*)d_in[16];
    const float* dbih  = (const float*)d_in[17];
    const float* dbhh  = (const float*)d_in[18];
    const float* Wu    = (const float*)d_in[19];
    const float* bu    = (const float*)d_in[20];
    float* out = (float*)d_out;

    float *xg, *seqA, *seqB;
    cudaGetSymbolAddress((void**)&xg,   g_xg);
    cudaGetSymbolAddress((void**)&seqA, g_seqA);
    cudaGetSymbolAddress((void**)&seqB, g_seqB);

    const size_t WSTRIDE = (size_t)GDIM * HDIM;
    const dim3 gBig(GDIM / 64, (BDIM * TDIM) / 64);

    // split all recurrent-side weights into bf16 hi/lo tiled form
    prep_w<<<2048, 256>>>(eWhh0, eWhh, eWhh + WSTRIDE,
                          dWhh0, dWih, dWih + WSTRIDE,
                          dWhh, dWhh + WSTRIDE);

    // encoder layer 0
    gemm_hoist<<<gBig, 256>>>(x, eWih0, IDIM, xg, BDIM * TDIM, GDIM);
    enc_layer_kernel<<<NBLK, NTHR>>>(W_EWH0, 0, ebih0, ebhh0, seqB);
    // encoder layer 1
    gemm_hoist<<<gBig, 256>>>(seqB, eWih, HDIM, xg, BDIM * TDIM, GDIM);
    enc_layer_kernel<<<NBLK, NTHR>>>(W_EWH1, 1, ebih, ebhh, seqA);
    // encoder layer 2
    gemm_hoist<<<gBig, 256>>>(seqA, eWih + WSTRIDE, HDIM, xg, BDIM * TDIM, GDIM);
    enc_layer_kernel<<<NBLK, NTHR>>>(W_EWH2, 2, ebih + GDIM, ebhh + GDIM, seqB);

    // decoder (persistent, all 511 steps)
    dec_kernel<<<NBLK, NTHR>>>(dWih0, dbih0, dbhh0, dbih, dbhh,
                               Wu, bu, y, force, out);
}

// round 12
// speedup vs baseline: 5.0830x; 1.0685x over previous
#include <cuda_runtime.h>
#include <cuda_bf16.h>
#include <math.h>
#include <stdint.h>
#include <stddef.h>

#define BDIM 128
#define TDIM 512
#define IDIM 32
#define HDIM 1024
#define GDIM 4096
#define BH   (BDIM*HDIM)
#define NBLK 128
#define NTHR 256
#define MSZ  4194304   // 4096*1024 elements per weight matrix

// weight slots in the bf16 tiled store
#define W_EWH0 0
#define W_EWH1 1
#define W_EWH2 2
#define W_DWH0 3
#define W_DWI1 4
#define W_DWI2 5
#define W_DWH1 6
#define W_DWH2 7
#define W_HWI1 8
#define W_HWI2 9
#define NWMAT  10

// ---------------- static device scratch (no allocations anywhere) ----------------
static __device__ __nv_bfloat16 g_whi[(size_t)NWMAT * MSZ];  // weights hi, tiled
static __device__ __nv_bfloat16 g_wlo[(size_t)NWMAT * MSZ];  // weights lo, tiled
static __device__ __nv_bfloat16 g_eh16[2][2][BH];            // encoder h ping-pong [par][hi/lo], tiled
static __device__ __nv_bfloat16 g_zero16[BH];                // never written -> zeros
static __device__ __nv_bfloat16 g_dh16[2][3][2][BH];         // decoder h [par][layer][hi/lo], tiled
static __device__ __nv_bfloat16 g_s16hi[(size_t)BDIM * TDIM * HDIM]; // seq acts hi, slab-tiled
static __device__ __nv_bfloat16 g_s16lo[(size_t)BDIM * TDIM * HDIM]; // seq acts lo, slab-tiled
static __device__ float g_h2f[BH];                           // decoder top-layer h fp32 (for head)
static __device__ float g_xg[(size_t)BDIM * TDIM * GDIM];    // hoisted input-gate preacts
static __device__ float g_cT[3 * BH];                        // encoder final c
static __device__ float g_xfeed[BDIM];
static __device__ unsigned g_count = 0;
static __device__ unsigned g_gen = 0;

// ---------------- software grid barrier (all NBLK blocks resident) ----------------
__device__ __forceinline__ void gsync() {
    __syncthreads();
    if (threadIdx.x == 0) {
        unsigned gen = *((volatile unsigned*)&g_gen);
        __threadfence();
        if (atomicAdd(&g_count, 1u) == gridDim.x - 1) {
            atomicExch(&g_count, 0u);
            __threadfence();
            *((volatile unsigned*)&g_gen) = gen + 1u;
        } else {
            while (*((volatile unsigned*)&g_gen) == gen) __nanosleep(64);
        }
        __threadfence();
    }
    __syncthreads();
}

__device__ __forceinline__ float sigm(float x) { return 1.f / (1.f + expf(-x)); }

// tiled index for an element (row, k) of a [4096(rows) x 1024(k)] matrix,
// 8x8 bf16 tiles, tile raster = row-tile-major then k-tile: lane-coalesced frags.
__device__ __forceinline__ uint32_t widx(int row, int k) {
    return (uint32_t)(row >> 3) * 8192u + (uint32_t)(k >> 3) * 64u
         + (uint32_t)(row & 7) * 8u + (uint32_t)(k & 7);
}
// same tiling for an H slab [128(rows) x 1024(k)]
__device__ __forceinline__ uint32_t hidx(int b, int u) {
    return (uint32_t)(b >> 3) * 8192u + (uint32_t)(u >> 3) * 64u
         + (uint32_t)(b & 7) * 8u + (uint32_t)(u & 7);
}

#define MMA16816(C, A0, A1, A2, A3, B0, B1) \
    asm volatile("mma.sync.aligned.m16n8k16.row.col.f32.bf16.bf16.f32 " \
        "{%0,%1,%2,%3}, {%4,%5,%6,%7}, {%8,%9}, {%0,%1,%2,%3};" \
        : "+f"((C)[0]), "+f"((C)[1]), "+f"((C)[2]), "+f"((C)[3]) \
        : "r"(A0), "r"(A1), "r"(A2), "r"(A3), "r"(B0), "r"(B1))

// ---------------- weight prep: fp32 -> bf16 hi/lo in tiled layout ----------------
__global__ void prep_w(const float* p0, const float* p1, const float* p2, const float* p3,
                       const float* p4, const float* p5, const float* p6, const float* p7,
                       const float* p8, const float* p9)
{
    for (size_t i = (size_t)blockIdx.x * blockDim.x + threadIdx.x;
         i < (size_t)NWMAT * MSZ; i += (size_t)gridDim.x * blockDim.x) {
        int m = (int)(i >> 22);
        int e = (int)(i & (MSZ - 1));
        const float* src;
        switch (m) {
            case 0: src = p0; break; case 1: src = p1; break;
            case 2: src = p2; break; case 3: src = p3; break;
            case 4: src = p4; break; case 5: src = p5; break;
            case 6: src = p6; break; case 7: src = p7; break;
            case 8: src = p8; break; default: src = p9; break;
        }
        float v = src[e];
        __nv_bfloat16 h = __float2bfloat16(v);
        __nv_bfloat16 l = __float2bfloat16(v - __bfloat162float(h));
        int row = e >> 10, k = e & 1023;
        size_t dst = (size_t)m * MSZ + widx(row, k);
        g_whi[dst] = h;
        g_wlo[dst] = l;
    }
}

// ---------------- block MMA: C[32 Wrows, 128 rows] += W @ H^T (3-term bf16) ----------------
__device__ __forceinline__ void accum_mma(
    const __nv_bfloat16* __restrict__ Whi, const __nv_bfloat16* __restrict__ Wlo,
    const __nv_bfloat16* __restrict__ Hhi, const __nv_bfloat16* __restrict__ Hlo,
    float C[4][4], int u0)
{
    const int tid = threadIdx.x;
    const int w = tid >> 5, lane = tid & 31;
    const int q0 = (w & 1) * 2;
    const int q1 = q0 + 1;
    const uint32_t lo2 = 2u * (uint32_t)lane;
    const uint32_t wb0 = (uint32_t)(q0 * 128 + (u0 >> 3)) * 8192u + lo2;
    const uint32_t wb1 = (uint32_t)(q1 * 128 + (u0 >> 3)) * 8192u + lo2;
    uint32_t hb[4];
#pragma unroll
    for (int j = 0; j < 4; j++)
        hb[j] = (uint32_t)((w >> 1) * 4 + j) * 8192u + lo2;

#pragma unroll 2
    for (int kt = 0; kt < 128; kt += 2) {
        const uint32_t ko = (uint32_t)kt * 64u;
        uint32_t ah0 = *(const uint32_t*)(Whi + wb0 + ko);
        uint32_t ah1 = *(const uint32_t*)(Whi + wb1 + ko);
        uint32_t ah2 = *(const uint32_t*)(Whi + wb0 + ko + 64);
        uint32_t ah3 = *(const uint32_t*)(Whi + wb1 + ko + 64);
        uint32_t al0 = *(const uint32_t*)(Wlo + wb0 + ko);
        uint32_t al1 = *(const uint32_t*)(Wlo + wb1 + ko);
        uint32_t al2 = *(const uint32_t*)(Wlo + wb0 + ko + 64);
        uint32_t al3 = *(const uint32_t*)(Wlo + wb1 + ko + 64);
#pragma unroll
        for (int j = 0; j < 4; j++) {
            uint32_t bh0 = *(const uint32_t*)(Hhi + hb[j] + ko);
            uint32_t bh1 = *(const uint32_t*)(Hhi + hb[j] + ko + 64);
            uint32_t bl0 = *(const uint32_t*)(Hlo + hb[j] + ko);
            uint32_t bl1 = *(const uint32_t*)(Hlo + hb[j] + ko + 64);
            MMA16816(C[j], ah0, ah1, ah2, ah3, bh0, bh1);  // hi*hi
            MMA16816(C[j], ah0, ah1, ah2, ah3, bl0, bl1);  // hi*lo
            MMA16816(C[j], al0, al1, al2, al3, bh0, bh1);  // lo*hi
        }
    }
}

// store C fragments into gates smem [r_local 32][row 128]; r_local = q*8 + unit_off
__device__ __forceinline__ void store_C(float C[4][4], float (*gates_s)[132])
{
    const int tid = threadIdx.x;
    const int w = tid >> 5, lane = tid & 31;
    const int g = lane >> 2, tg = lane & 3;
    const int r0 = (w & 1) * 16 + g;
    const int r1 = r0 + 8;
#pragma unroll
    for (int j = 0; j < 4; j++) {
        const int cb = (w >> 1) * 32 + j * 8 + 2 * tg;
        gates_s[r0][cb]     = C[j][0];
        gates_s[r0][cb + 1] = C[j][1];
        gates_s[r1][cb]     = C[j][2];
        gates_s[r1][cb + 1] = C[j][3];
    }
}

// ---------------- bf16 MMA hoist GEMM: xg[slab] = W @ Sact[slab]^T ----------------
__global__ void __launch_bounds__(NTHR, 2) hoist_mma(int wslot)
{
    __shared__ float gates_s[32][132];
    const int u0 = blockIdx.x * 8;
    const int slab = blockIdx.y;
    const size_t sb = (size_t)slab * 131072;   // 128 rows x 1024

    float C[4][4];
#pragma unroll
    for (int a = 0; a < 4; a++)
#pragma unroll
        for (int b = 0; b < 4; b++) C[a][b] = 0.f;

    accum_mma(g_whi + (size_t)wslot * MSZ, g_wlo + (size_t)wslot * MSZ,
              g_s16hi + sb, g_s16lo + sb, C, u0);
    store_C(C, gates_s);
    __syncthreads();

    const int tid = threadIdx.x;
#pragma unroll
    for (int pass = 0; pass < 16; pass++) {
        const int idx = pass * 256 + tid;
        const int uo = idx & 7, q = (idx >> 3) & 3, row = idx >> 5;
        g_xg[((size_t)slab * 128 + row) * GDIM + (q << 10) + u0 + uo]
            = gates_s[q * 8 + uo][row];
    }
}

// ---------------- persistent encoder layer ----------------
__global__ void __launch_bounds__(NTHR, 1) enc_layer_kernel(
    int wslot, int dslot,
    const float* __restrict__ bih, const float* __restrict__ bhh,
    int write_seq)
{
    __shared__ float gates_s[32][132];
    const int tid = threadIdx.x;
    const int u0 = blockIdx.x * 8;
    const int j = tid >> 5, bl = tid & 31;
    const int u = u0 + j;
    const __nv_bfloat16* Whi = g_whi + (size_t)wslot * MSZ;
    const __nv_bfloat16* Wlo = g_wlo + (size_t)wslot * MSZ;

    float bs[4];
#pragma unroll
    for (int q = 0; q < 4; q++) bs[q] = bih[(q << 10) + u] + bhh[(q << 10) + u];

    float cl[4] = {0.f, 0.f, 0.f, 0.f};
    float hl[4] = {0.f, 0.f, 0.f, 0.f};

#pragma unroll 1
    for (int t = 0; t < TDIM; t++) {
        float C[4][4];
#pragma unroll
        for (int a = 0; a < 4; a++)
#pragma unroll
            for (int b = 0; b < 4; b++) C[a][b] = 0.f;

        const __nv_bfloat16* Hhi = t ? &g_eh16[t & 1][0][0] : g_zero16;
        const __nv_bfloat16* Hlo = t ? &g_eh16[t & 1][1][0] : g_zero16;
        accum_mma(Whi, Wlo, Hhi, Hlo, C, u0);
        store_C(C, gates_s);
        __syncthreads();

        const int wp = (t + 1) & 1;
#pragma unroll
        for (int i = 0; i < 4; i++) {
            const int b = bl + 32 * i;
            const size_t xr = ((size_t)b * TDIM + t) * GDIM;
            float ip = gates_s[j][b]      + g_xg[xr + u]        + bs[0];
            float fp = gates_s[8 + j][b]  + g_xg[xr + 1024 + u] + bs[1];
            float gp = gates_s[16 + j][b] + g_xg[xr + 2048 + u] + bs[2];
            float op = gates_s[24 + j][b] + g_xg[xr + 3072 + u] + bs[3];
            float cn = sigm(fp) * cl[i] + sigm(ip) * tanhf(gp);
            float hn = sigm(op) * tanhf(cn);
            cl[i] = cn; hl[i] = hn;
            __nv_bfloat16 hh = __float2bfloat16(hn);
            __nv_bfloat16 hlo = __float2bfloat16(hn - __bfloat162float(hh));
            const uint32_t hd = hidx(b, u);
            g_eh16[wp][0][hd] = hh;
            g_eh16[wp][1][hd] = hlo;
            if (write_seq) {
                const int r = b * TDIM + t;
                const size_t sd = (size_t)(r >> 7) * 131072 + hidx(t & 127, u);
                g_s16hi[sd] = hh;
                g_s16lo[sd] = hlo;
            }
        }
        gsync();
    }
    // export final states for the decoder
#pragma unroll
    for (int i = 0; i < 4; i++) {
        const int b = bl + 32 * i;
        g_cT[dslot * BH + b * HDIM + u] = cl[i];
        __nv_bfloat16 hh = __float2bfloat16(hl[i]);
        __nv_bfloat16 hlo = __float2bfloat16(hl[i] - __bfloat162float(hh));
        const uint32_t hd = hidx(b, u);
        g_dh16[0][dslot][0][hd] = hh;
        g_dh16[0][dslot][1][hd] = hlo;
    }
}

// ---------------- persistent decoder ----------------
__global__ void __launch_bounds__(NTHR, 1) dec_kernel(
    const float* __restrict__ dWih0,
    const float* __restrict__ dbih0, const float* __restrict__ dbhh0,
    const float* __restrict__ dbih,  const float* __restrict__ dbhh,
    const float* __restrict__ Wu,    const float* __restrict__ bu,
    const float* __restrict__ y,     const int* __restrict__ force,
    float* __restrict__ out)
{
    __shared__ float gates_s[32][132];
    __shared__ float red2[8];
    const int tid = threadIdx.x;
    const int u0 = blockIdx.x * 8;
    const int j = tid >> 5, bl = tid & 31;
    const int u = u0 + j;

    float bs0[4], bs1[4], bs2[4], wc0[4];
#pragma unroll
    for (int q = 0; q < 4; q++) {
        const int g = (q << 10) + u;
        bs0[q] = dbih0[g] + dbhh0[g];
        bs1[q] = dbih[g] + dbhh[g];
        bs2[q] = dbih[GDIM + g] + dbhh[GDIM + g];
        wc0[q] = dWih0[g];
    }
    float c0[4], c1[4], c2[4];
#pragma unroll
    for (int i = 0; i < 4; i++) {
        const int b = bl + 32 * i;
        c0[i] = g_cT[0 * BH + b * HDIM + u];
        c1[i] = g_cT[1 * BH + b * HDIM + u];
        c2[i] = g_cT[2 * BH + b * HDIM + u];
    }
    if (blockIdx.x == 0 && tid < BDIM) {
        g_xfeed[tid] = y[(size_t)tid * TDIM];
        out[(size_t)tid * TDIM] = 0.f;     // output[:,0] = 0
    }
    gsync();

#pragma unroll 1
    for (int s = 0; s < TDIM - 1; s++) {
        const int p = s & 1;
        float C[4][4];

        // ----- layer 0: gates = h0 @ Whh0^T (+ xfeed*Wih0 + b) -----
#pragma unroll
        for (int a = 0; a < 4; a++)
#pragma unroll
            for (int b = 0; b < 4; b++) C[a][b] = 0.f;
        accum_mma(g_whi + (size_t)W_DWH0 * MSZ, g_wlo + (size_t)W_DWH0 * MSZ,
                  &g_dh16[p][0][0][0], &g_dh16[p][0][1][0], C, u0);
        store_C(C, gates_s);
        __syncthreads();
#pragma unroll
        for (int i = 0; i < 4; i++) {
            const int b = bl + 32 * i;
            const float xf = g_xfeed[b];
            float ip = gates_s[j][b]      + xf * wc0[0] + bs0[0];
            float fp = gates_s[8 + j][b]  + xf * wc0[1] + bs0[1];
            float gp = gates_s[16 + j][b] + xf * wc0[2] + bs0[2];
            float op = gates_s[24 + j][b] + xf * wc0[3] + bs0[3];
            float cn = sigm(fp) * c0[i] + sigm(ip) * tanhf(gp);
            float hn = sigm(op) * tanhf(cn);
            c0[i] = cn;
            __nv_bfloat16 hh = __float2bfloat16(hn);
            __nv_bfloat16 hlo = __float2bfloat16(hn - __bfloat162float(hh));
            const uint32_t hd = hidx(b, u);
            g_dh16[p ^ 1][0][0][hd] = hh;
            g_dh16[p ^ 1][0][1][hd] = hlo;
        }
        gsync();

        // ----- layer 1: gates = h0_new @ Wih1^T + h1 @ Whh1^T -----
#pragma unroll
        for (int a = 0; a < 4; a++)
#pragma unroll
            for (int b = 0; b < 4; b++) C[a][b] = 0.f;
        accum_mma(g_whi + (size_t)W_DWI1 * MSZ, g_wlo + (size_t)W_DWI1 * MSZ,
                  &g_dh16[p ^ 1][0][0][0], &g_dh16[p ^ 1][0][1][0], C, u0);
        accum_mma(g_whi + (size_t)W_DWH1 * MSZ, g_wlo + (size_t)W_DWH1 * MSZ,
                  &g_dh16[p][1][0][0], &g_dh16[p][1][1][0], C, u0);
        store_C(C, gates_s);
        __syncthreads();
#pragma unroll
        for (int i = 0; i < 4; i++) {
            const int b = bl + 32 * i;
            float ip = gates_s[j][b]      + bs1[0];
            float fp = gates_s[8 + j][b]  + bs1[1];
            float gp = gates_s[16 + j][b] + bs1[2];
            float op = gates_s[24 + j][b] + bs1[3];
            float cn = sigm(fp) * c1[i] + sigm(ip) * tanhf(gp);
            float hn = sigm(op) * tanhf(cn);
            c1[i] = cn;
            __nv_bfloat16 hh = __float2bfloat16(hn);
            __nv_bfloat16 hlo = __float2bfloat16(hn - __bfloat162float(hh));
            const uint32_t hd = hidx(b, u);
            g_dh16[p ^ 1][1][0][hd] = hh;
            g_dh16[p ^ 1][1][1][hd] = hlo;
        }
        gsync();

        // ----- layer 2 -----
#pragma unroll
        for (int a = 0; a < 4; a++)
#pragma unroll
            for (int b = 0; b < 4; b++) C[a][b] = 0.f;
        accum_mma(g_whi + (size_t)W_DWI2 * MSZ, g_wlo + (size_t)W_DWI2 * MSZ,
                  &g_dh16[p ^ 1][1][0][0], &g_dh16[p ^ 1][1][1][0], C, u0);
        accum_mma(g_whi + (size_t)W_DWH2 * MSZ, g_wlo + (size_t)W_DWH2 * MSZ,
                  &g_dh16[p][2][0][0], &g_dh16[p][2][1][0], C, u0);
        store_C(C, gates_s);
        __syncthreads();
#pragma unroll
        for (int i = 0; i < 4; i++) {
            const int b = bl + 32 * i;
            float ip = gates_s[j][b]      + bs2[0];
            float fp = gates_s[8 + j][b]  + bs2[1];
            float gp = gates_s[16 + j][b] + bs2[2];
            float op = gates_s[24 + j][b] + bs2[3];
            float cn = sigm(fp) * c2[i] + sigm(ip) * tanhf(gp);
            float hn = sigm(op) * tanhf(cn);
            c2[i] = cn;
            g_h2f[b * HDIM + u] = hn;
            __nv_bfloat16 hh = __float2bfloat16(hn);
            __nv_bfloat16 hlo = __float2bfloat16(hn - __bfloat162float(hh));
            const uint32_t hd = hidx(b, u);
            g_dh16[p ^ 1][2][0][hd] = hh;
            g_dh16[p ^ 1][2][1][hd] = hlo;
        }
        gsync();

        // ----- output head + teacher forcing: block b handles batch row b -----
        {
            const float* hr = g_h2f + (size_t)blockIdx.x * HDIM;
            float a = 0.f;
#pragma unroll 4
            for (int k = tid; k < HDIM; k += NTHR) a += hr[k] * Wu[k];
#pragma unroll
            for (int o = 16; o; o >>= 1) a += __shfl_xor_sync(0xFFFFFFFFu, a, o);
            if ((tid & 31) == 0) red2[tid >> 5] = a;
            __syncthreads();
            if (tid == 0) {
                float ov = bu[0];
#pragma unroll
                for (int ww = 0; ww < 8; ww++) ov += red2[ww];
                out[(size_t)blockIdx.x * TDIM + s + 1] = ov;
                g_xfeed[blockIdx.x] = (force[s] > 0) ? y[(size_t)blockIdx.x * TDIM + s + 1] : ov;
            }
        }
        gsync();
    }
}

// ---------------- fp32 NT GEMM for the tiny K=32 layer-0 hoist ----------------
__global__ void __launch_bounds__(256) gemm_hoist(
    const float* __restrict__ A, const float* __restrict__ B, int K,
    float* __restrict__ C, int M, int N)
{
    __shared__ float As[16][68];
    __shared__ float Bs[16][68];
    const int tid = threadIdx.x;
    const int tx = tid & 15, ty = tid >> 4;
    const int m0 = blockIdx.y * 64, n0 = blockIdx.x * 64;
    const int lr = tid >> 2;
    const int lc = (tid & 3) * 4;

    float acc[4][4];
#pragma unroll
    for (int i = 0; i < 4; i++)
#pragma unroll
        for (int jj = 0; jj < 4; jj++) acc[i][jj] = 0.f;

#pragma unroll 1
    for (int k0 = 0; k0 < K; k0 += 16) {
        float4 av = *(const float4*)&A[(size_t)(m0 + lr) * K + k0 + lc];
        float4 bv = *(const float4*)&B[(size_t)(n0 + lr) * K + k0 + lc];
        __syncthreads();
        As[lc + 0][lr] = av.x; As[lc + 1][lr] = av.y; As[lc + 2][lr] = av.z; As[lc + 3][lr] = av.w;
        Bs[lc + 0][lr] = bv.x; Bs[lc + 1][lr] = bv.y; Bs[lc + 2][lr] = bv.z; Bs[lc + 3][lr] = bv.w;
        __syncthreads();
#pragma unroll
        for (int k = 0; k < 16; k++) {
            float4 a = *(const float4*)&As[k][ty * 4];
            float4 b = *(const float4*)&Bs[k][tx * 4];
            acc[0][0] += a.x * b.x; acc[0][1] += a.x * b.y; acc[0][2] += a.x * b.z; acc[0][3] += a.x * b.w;
            acc[1][0] += a.y * b.x; acc[1][1] += a.y * b.y; acc[1][2] += a.y * b.z; acc[1][3] += a.y * b.w;
            acc[2][0] += a.z * b.x; acc[2][1] += a.z * b.y; acc[2][2] += a.z * b.z; acc[2][3] += a.z * b.w;
            acc[3][0] += a.w * b.x; acc[3][1] += a.w * b.y; acc[3][2] += a.w * b.z; acc[3][3] += a.w * b.w;
        }
    }
#pragma unroll
    for (int i = 0; i < 4; i++) {
        float4 v = make_float4(acc[i][0], acc[i][1], acc[i][2], acc[i][3]);
        *(float4*)&C[(size_t)(m0 + ty * 4 + i) * N + n0 + tx * 4] = v;
    }
}

// ---------------- host orchestration: 8 graph nodes ----------------
extern "C" void kernel_launch(void* const* d_in, const int* in_sizes, int n_in,
                              void* d_out, int out_size)
{
    (void)in_sizes; (void)n_in; (void)out_size;

    const float* x     = (const float*)d_in[0];
    const float* y     = (const float*)d_in[1];
    const int*   force = (const int*)  d_in[2];
    const float* eWih0 = (const float*)d_in[3];
    const float* eWhh0 = (const float*)d_in[4];
    const float* ebih0 = (const float*)d_in[5];
    const float* ebhh0 = (const float*)d_in[6];
    const float* eWih  = (const float*)d_in[7];
    const float* eWhh  = (const float*)d_in[8];
    const float* ebih  = (const float*)d_in[9];
    const float* ebhh  = (const float*)d_in[10];
    const float* dWih0 = (const float*)d_in[11];
    const float* dWhh0 = (const float*)d_in[12];
    const float* dbih0 = (const float*)d_in[13];
    const float* dbhh0 = (const float*)d_in[14];
    const float* dWih  = (const float*)d_in[15];
    const float* dWhh  = (const float*)d_in[16];
    const float* dbih  = (const float*)d_in[17];
    const float* dbhh  = (const float*)d_in[18];
    const float* Wu    = (const float*)d_in[19];
    const float* bu    = (const float*)d_in[20];
    float* out = (float*)d_out;

    float* xg;
    cudaGetSymbolAddress((void**)&xg, g_xg);

    const size_t WSTRIDE = (size_t)GDIM * HDIM;
    const dim3 gBig(GDIM / 64, (BDIM * TDIM) / 64);
    const dim3 gHoist(HDIM / 8, (BDIM * TDIM) / 128);

    // split all recurrent + hoist weights into bf16 hi/lo tiled form
    prep_w<<<2048, 256>>>(eWhh0, eWhh, eWhh + WSTRIDE,
                          dWhh0, dWih, dWih + WSTRIDE,
                          dWhh, dWhh + WSTRIDE,
                          eWih, eWih + WSTRIDE);

    // encoder layer 0 (input hoist is tiny K=32 fp32 GEMM)
    gemm_hoist<<<gBig, 256>>>(x, eWih0, IDIM, xg, BDIM * TDIM, GDIM);
    enc_layer_kernel<<<NBLK, NTHR>>>(W_EWH0, 0, ebih0, ebhh0, /*write_seq=*/1);
    // encoder layer 1
    hoist_mma<<<gHoist, NTHR>>>(W_HWI1);
    enc_layer_kernel<<<NBLK, NTHR>>>(W_EWH1, 1, ebih, ebhh, /*write_seq=*/1);
    // encoder layer 2
    hoist_mma<<<gHoist, NTHR>>>(W_HWI2);
    enc_layer_kernel<<<NBLK, NTHR>>>(W_EWH2, 2, ebih + GDIM, ebhh + GDIM, /*write_seq=*/0);

    // decoder (persistent, all 511 steps)
    dec_kernel<<<NBLK, NTHR>>>(dWih0, dbih0, dbhh0, dbih, dbhh,
                               Wu, bu, y, force, out);
}

// round 13
// speedup vs baseline: 5.2410x; 1.0311x over previous
#include <cuda_runtime.h>
#include <cuda_bf16.h>
#include <math.h>
#include <stdint.h>
#include <stddef.h>

#define BDIM 128
#define TDIM 512
#define IDIM 32
#define HDIM 1024
#define GDIM 4096
#define BH   (BDIM*HDIM)
#define NBLK 128
#define NTHR 256
#define MSZ  4194304        // 4096*1024 elements per weight matrix
#define WREC 1048576        // uint4 records per weight matrix (MSZ/4)
#define HREC 32768          // uint4 records per H buffer (128*1024/4)

// weight slots in the packed store
#define W_EWH0 0
#define W_EWH1 1
#define W_EWH2 2
#define W_DWH0 3
#define W_DWI1 4
#define W_DWI2 5
#define W_DWH1 6
#define W_DWH2 7
#define W_HWI1 8
#define W_HWI2 9
#define NWMAT  10

// ---------------- static device scratch (no allocations anywhere) ----------------
// Packed record layout (16 B per lane-record = 4 elements' hi+lo):
//   bf16[0..1] = hi of k-tile t0 (elements 2p, 2p+1)
//   bf16[2..3] = hi of k-tile t1
//   bf16[4..5] = lo of k-tile t0
//   bf16[6..7] = lo of k-tile t1
static __device__ uint4 g_w4[(size_t)NWMAT * WREC];          // packed weights (160 MB)
static __device__ uint4 g_eh4[2][HREC];                      // encoder h ping-pong
static __device__ uint4 g_z4[HREC];                          // never written -> zeros
static __device__ uint4 g_dh4[2][3][HREC];                   // decoder h [par][layer]
static __device__ uint4 g_s4[(size_t)512 * HREC];            // seq activations, slab-packed (256 MB)
static __device__ float g_h2f[BH];                           // decoder top-layer h fp32 (head)
static __device__ float g_xg[(size_t)BDIM * TDIM * GDIM];    // hoisted input-gate preacts (1 GB)
static __device__ float g_cT[3 * BH];                        // encoder final c
static __device__ float g_xfeed[BDIM];
static __device__ unsigned g_count = 0;
static __device__ unsigned g_gen = 0;

// ---------------- software grid barrier (all NBLK blocks resident) ----------------
__device__ __forceinline__ void gsync() {
    __syncthreads();
    if (threadIdx.x == 0) {
        unsigned gen = *((volatile unsigned*)&g_gen);
        __threadfence();
        if (atomicAdd(&g_count, 1u) == gridDim.x - 1) {
            atomicExch(&g_count, 0u);
            __threadfence();
            *((volatile unsigned*)&g_gen) = gen + 1u;
        } else {
            while (*((volatile unsigned*)&g_gen) == gen) __nanosleep(64);
        }
        __threadfence();
    }
    __syncthreads();
}

__device__ __forceinline__ float sigm(float x) { return 1.f / (1.f + expf(-x)); }

#define MMA16816(C, A0, A1, A2, A3, B0, B1) \
    asm volatile("mma.sync.aligned.m16n8k16.row.col.f32.bf16.bf16.f32 " \
        "{%0,%1,%2,%3}, {%4,%5,%6,%7}, {%8,%9}, {%0,%1,%2,%3};" \
        : "+f"((C)[0]), "+f"((C)[1]), "+f"((C)[2]), "+f"((C)[3]) \
        : "r"(A0), "r"(A1), "r"(A2), "r"(A3), "r"(B0), "r"(B1))

// write one fp32 value as packed hi/lo bf16 into an H-style record array.
// rows = "b" dimension (8-row tiles), cols = "u"/k dimension (16-k record groups).
__device__ __forceinline__ void put_h(uint4* H4, int b, int u, float hn) {
    __nv_bfloat16 hh = __float2bfloat16(hn);
    __nv_bfloat16 hl = __float2bfloat16(hn - __bfloat162float(hh));
    const int t01 = (u >> 3) & 1, half = u & 1;
    __nv_bfloat16* p = (__nv_bfloat16*)(H4 + ((size_t)((b >> 3) * 64 + (u >> 4)) * 32
                                              + (b & 7) * 4 + ((u & 7) >> 1)));
    p[t01 * 2 + half]     = hh;
    p[4 + t01 * 2 + half] = hl;
}

// ---------------- weight prep: fp32 -> packed hi/lo records ----------------
__global__ void prep_w(const float* p0, const float* p1, const float* p2, const float* p3,
                       const float* p4, const float* p5, const float* p6, const float* p7,
                       const float* p8, const float* p9)
{
    for (size_t i = (size_t)blockIdx.x * blockDim.x + threadIdx.x;
         i < (size_t)NWMAT * MSZ; i += (size_t)gridDim.x * blockDim.x) {
        int m = (int)(i >> 22);
        int e = (int)(i & (MSZ - 1));
        const float* src;
        switch (m) {
            case 0: src = p0; break; case 1: src = p1; break;
            case 2: src = p2; break; case 3: src = p3; break;
            case 4: src = p4; break; case 5: src = p5; break;
            case 6: src = p6; break; case 7: src = p7; break;
            case 8: src = p8; break; default: src = p9; break;
        }
        float v = src[e];
        __nv_bfloat16 h = __float2bfloat16(v);
        __nv_bfloat16 l = __float2bfloat16(v - __bfloat162float(h));
        int row = e >> 10, k = e & 1023;
        uint4* rec = g_w4 + (size_t)m * WREC
                   + ((size_t)((row >> 3) * 64 + (k >> 4)) * 32
                      + (row & 7) * 4 + ((k & 7) >> 1));
        __nv_bfloat16* p = (__nv_bfloat16*)rec;
        const int t01 = (k >> 3) & 1, half = k & 1;
        p[t01 * 2 + half]     = h;
        p[4 + t01 * 2 + half] = l;
    }
}

// ---------------- block MMA: C[32 Wrows, 128 rows] += W @ H^T (3-term bf16) ----------------
// One uint4 load per lane = all 4 fragment regs (hi t0, hi t1, lo t0, lo t1).
__device__ __forceinline__ void accum_mma(
    const uint4* __restrict__ W4, const uint4* __restrict__ H4,
    float C[4][4], int u0)
{
    const int tid = threadIdx.x;
    const int w = tid >> 5, lane = tid & 31;
    const int q0 = (w & 1) * 2, q1 = q0 + 1;
    const uint32_t rb0 = (uint32_t)(q0 * 128 + (u0 >> 3)) * 2048u + (uint32_t)lane;
    const uint32_t rb1 = (uint32_t)(q1 * 128 + (u0 >> 3)) * 2048u + (uint32_t)lane;
    uint32_t hb[4];
#pragma unroll
    for (int j = 0; j < 4; j++)
        hb[j] = (uint32_t)((w >> 1) * 4 + j) * 2048u + (uint32_t)lane;

#pragma unroll 2
    for (int kt2 = 0; kt2 < 64; kt2++) {
        const uint32_t ko = (uint32_t)kt2 * 32u;
        uint4 wa = W4[rb0 + ko];     // A frags gate q0: hi t0, hi t1, lo t0, lo t1
        uint4 wb = W4[rb1 + ko];     // A frags gate q1
#pragma unroll
        for (int j = 0; j < 4; j++) {
            uint4 h = H4[hb[j] + ko];  // B frags: hi t0, hi t1, lo t0, lo t1
            MMA16816(C[j], wa.x, wb.x, wa.y, wb.y, h.x, h.y);  // hi*hi
            MMA16816(C[j], wa.x, wb.x, wa.y, wb.y, h.z, h.w);  // hi*lo
            MMA16816(C[j], wa.z, wb.z, wa.w, wb.w, h.x, h.y);  // lo*hi
        }
    }
}

// store C fragments into gates smem [r_local 32][row 128]; r_local = q*8 + unit_off
__device__ __forceinline__ void store_C(float C[4][4], float (*gates_s)[132])
{
    const int tid = threadIdx.x;
    const int w = tid >> 5, lane = tid & 31;
    const int g = lane >> 2, tg = lane & 3;
    const int r0 = (w & 1) * 16 + g;
    const int r1 = r0 + 8;
#pragma unroll
    for (int j = 0; j < 4; j++) {
        const int cb = (w >> 1) * 32 + j * 8 + 2 * tg;
        gates_s[r0][cb]     = C[j][0];
        gates_s[r0][cb + 1] = C[j][1];
        gates_s[r1][cb]     = C[j][2];
        gates_s[r1][cb + 1] = C[j][3];
    }
}

// ---------------- bf16 MMA hoist GEMM: xg[slab] = W @ Sact[slab]^T ----------------
__global__ void __launch_bounds__(NTHR, 2) hoist_mma(int wslot)
{
    __shared__ float gates_s[32][132];
    const int u0 = blockIdx.x * 8;
    const int slab = blockIdx.y;

    float C[4][4];
#pragma unroll
    for (int a = 0; a < 4; a++)
#pragma unroll
        for (int b = 0; b < 4; b++) C[a][b] = 0.f;

    accum_mma(g_w4 + (size_t)wslot * WREC, g_s4 + (size_t)slab * HREC, C, u0);
    store_C(C, gates_s);
    __syncthreads();

    const int tid = threadIdx.x;
#pragma unroll
    for (int pass = 0; pass < 16; pass++) {
        const int idx = pass * 256 + tid;
        const int uo = idx & 7, q = (idx >> 3) & 3, row = idx >> 5;
        g_xg[((size_t)slab * 128 + row) * GDIM + (q << 10) + u0 + uo]
            = gates_s[q * 8 + uo][row];
    }
}

// ---------------- persistent encoder layer ----------------
__global__ void __launch_bounds__(NTHR, 1) enc_layer_kernel(
    int wslot, int dslot,
    const float* __restrict__ bih, const float* __restrict__ bhh,
    int write_seq)
{
    __shared__ float gates_s[32][132];
    const int tid = threadIdx.x;
    const int u0 = blockIdx.x * 8;
    const int j = tid >> 5, bl = tid & 31;
    const int u = u0 + j;
    const uint4* W4 = g_w4 + (size_t)wslot * WREC;

    float bs[4];
#pragma unroll
    for (int q = 0; q < 4; q++) bs[q] = bih[(q << 10) + u] + bhh[(q << 10) + u];

    float cl[4] = {0.f, 0.f, 0.f, 0.f};
    float hl[4] = {0.f, 0.f, 0.f, 0.f};

#pragma unroll 1
    for (int t = 0; t < TDIM; t++) {
        float C[4][4];
#pragma unroll
        for (int a = 0; a < 4; a++)
#pragma unroll
            for (int b = 0; b < 4; b++) C[a][b] = 0.f;

        const uint4* H = t ? g_eh4[t & 1] : g_z4;
        accum_mma(W4, H, C, u0);
        store_C(C, gates_s);
        __syncthreads();

        const int wp = (t + 1) & 1;
#pragma unroll
        for (int i = 0; i < 4; i++) {
            const int b = bl + 32 * i;
            const size_t xr = ((size_t)b * TDIM + t) * GDIM;
            float ip = gates_s[j][b]      + g_xg[xr + u]        + bs[0];
            float fp = gates_s[8 + j][b]  + g_xg[xr + 1024 + u] + bs[1];
            float gp = gates_s[16 + j][b] + g_xg[xr + 2048 + u] + bs[2];
            float op = gates_s[24 + j][b] + g_xg[xr + 3072 + u] + bs[3];
            float cn = sigm(fp) * cl[i] + sigm(ip) * tanhf(gp);
            float hn = sigm(op) * tanhf(cn);
            cl[i] = cn; hl[i] = hn;
            put_h(g_eh4[wp], b, u, hn);
            if (write_seq) {
                const int r = b * TDIM + t;
                put_h(g_s4 + (size_t)(r >> 7) * HREC, t & 127, u, hn);
            }
        }
        gsync();
    }
    // export final states for the decoder
#pragma unroll
    for (int i = 0; i < 4; i++) {
        const int b = bl + 32 * i;
        g_cT[dslot * BH + b * HDIM + u] = cl[i];
        put_h(&g_dh4[0][dslot][0], b, u, hl[i]);
    }
}

// ---------------- persistent decoder ----------------
__global__ void __launch_bounds__(NTHR, 1) dec_kernel(
    const float* __restrict__ dWih0,
    const float* __restrict__ dbih0, const float* __restrict__ dbhh0,
    const float* __restrict__ dbih,  const float* __restrict__ dbhh,
    const float* __restrict__ Wu,    const float* __restrict__ bu,
    const float* __restrict__ y,     const int* __restrict__ force,
    float* __restrict__ out)
{
    __shared__ float gates_s[32][132];
    __shared__ float red2[8];
    const int tid = threadIdx.x;
    const int u0 = blockIdx.x * 8;
    const int j = tid >> 5, bl = tid & 31;
    const int u = u0 + j;

    float bs0[4], bs1[4], bs2[4], wc0[4];
#pragma unroll
    for (int q = 0; q < 4; q++) {
        const int g = (q << 10) + u;
        bs0[q] = dbih0[g] + dbhh0[g];
        bs1[q] = dbih[g] + dbhh[g];
        bs2[q] = dbih[GDIM + g] + dbhh[GDIM + g];
        wc0[q] = dWih0[g];
    }
    float c0[4], c1[4], c2[4];
#pragma unroll
    for (int i = 0; i < 4; i++) {
        const int b = bl + 32 * i;
        c0[i] = g_cT[0 * BH + b * HDIM + u];
        c1[i] = g_cT[1 * BH + b * HDIM + u];
        c2[i] = g_cT[2 * BH + b * HDIM + u];
    }
    if (blockIdx.x == 0 && tid < BDIM) {
        g_xfeed[tid] = y[(size_t)tid * TDIM];
        out[(size_t)tid * TDIM] = 0.f;     // output[:,0] = 0
    }
    gsync();

#pragma unroll 1
    for (int s = 0; s < TDIM - 1; s++) {
        const int p = s & 1;
        float C[4][4];

        // ----- layer 0: gates = h0 @ Whh0^T (+ xfeed*Wih0 + b) -----
#pragma unroll
        for (int a = 0; a < 4; a++)
#pragma unroll
            for (int b = 0; b < 4; b++) C[a][b] = 0.f;
        accum_mma(g_w4 + (size_t)W_DWH0 * WREC, &g_dh4[p][0][0], C, u0);
        store_C(C, gates_s);
        __syncthreads();
#pragma unroll
        for (int i = 0; i < 4; i++) {
            const int b = bl + 32 * i;
            const float xf = g_xfeed[b];
            float ip = gates_s[j][b]      + xf * wc0[0] + bs0[0];
            float fp = gates_s[8 + j][b]  + xf * wc0[1] + bs0[1];
            float gp = gates_s[16 + j][b] + xf * wc0[2] + bs0[2];
            float op = gates_s[24 + j][b] + xf * wc0[3] + bs0[3];
            float cn = sigm(fp) * c0[i] + sigm(ip) * tanhf(gp);
            float hn = sigm(op) * tanhf(cn);
            c0[i] = cn;
            put_h(&g_dh4[p ^ 1][0][0], b, u, hn);
        }
        gsync();

        // ----- layer 1: gates = h0_new @ Wih1^T + h1 @ Whh1^T -----
#pragma unroll
        for (int a = 0; a < 4; a++)
#pragma unroll
            for (int b = 0; b < 4; b++) C[a][b] = 0.f;
        accum_mma(g_w4 + (size_t)W_DWI1 * WREC, &g_dh4[p ^ 1][0][0], C, u0);
        accum_mma(g_w4 + (size_t)W_DWH1 * WREC, &g_dh4[p][1][0], C, u0);
        store_C(C, gates_s);
        __syncthreads();
#pragma unroll
        for (int i = 0; i < 4; i++) {
            const int b = bl + 32 * i;
            float ip = gates_s[j][b]      + bs1[0];
            float fp = gates_s[8 + j][b]  + bs1[1];
            float gp = gates_s[16 + j][b] + bs1[2];
            float op = gates_s[24 + j][b] + bs1[3];
            float cn = sigm(fp) * c1[i] + sigm(ip) * tanhf(gp);
            float hn = sigm(op) * tanhf(cn);
            c1[i] = cn;
            put_h(&g_dh4[p ^ 1][1][0], b, u, hn);
        }
        gsync();

        // ----- layer 2 -----
#pragma unroll
        for (int a = 0; a < 4; a++)
#pragma unroll
            for (int b = 0; b < 4; b++) C[a][b] = 0.f;
        accum_mma(g_w4 + (size_t)W_DWI2 * WREC, &g_dh4[p ^ 1][1][0], C, u0);
        accum_mma(g_w4 + (size_t)W_DWH2 * WREC, &g_dh4[p][2][0], C, u0);
        store_C(C, gates_s);
        __syncthreads();
#pragma unroll
        for (int i = 0; i < 4; i++) {
            const int b = bl + 32 * i;
            float ip = gates_s[j][b]      + bs2[0];
            float fp = gates_s[8 + j][b]  + bs2[1];
            float gp = gates_s[16 + j][b] + bs2[2];
            float op = gates_s[24 + j][b] + bs2[3];
            float cn = sigm(fp) * c2[i] + sigm(ip) * tanhf(gp);
            float hn = sigm(op) * tanhf(cn);
            c2[i] = cn;
            g_h2f[b * HDIM + u] = hn;
            put_h(&g_dh4[p ^ 1][2][0], b, u, hn);
        }
        gsync();

        // ----- output head + teacher forcing: block b handles batch row b -----
        {
            const float* hr = g_h2f + (size_t)blockIdx.x * HDIM;
            float a = 0.f;
#pragma unroll 4
            for (int k = tid; k < HDIM; k += NTHR) a += hr[k] * Wu[k];
#pragma unroll
            for (int o = 16; o; o >>= 1) a += __shfl_xor_sync(0xFFFFFFFFu, a, o);
            if ((tid & 31) == 0) red2[tid >> 5] = a;
            __syncthreads();
            if (tid == 0) {
                float ov = bu[0];
#pragma unroll
                for (int ww = 0; ww < 8; ww++) ov += red2[ww];
                out[(size_t)blockIdx.x * TDIM + s + 1] = ov;
                g_xfeed[blockIdx.x] = (force[s] > 0) ? y[(size_t)blockIdx.x * TDIM + s + 1] : ov;
            }
        }
        gsync();
    }
}

// ---------------- fp32 NT GEMM for the tiny K=32 layer-0 hoist ----------------
__global__ void __launch_bounds__(256) gemm_hoist(
    const float* __restrict__ A, const float* __restrict__ B, int K,
    float* __restrict__ C, int M, int N)
{
    __shared__ float As[16][68];
    __shared__ float Bs[16][68];
    const int tid = threadIdx.x;
    const int tx = tid & 15, ty = tid >> 4;
    const int m0 = blockIdx.y * 64, n0 = blockIdx.x * 64;
    const int lr = tid >> 2;
    const int lc = (tid & 3) * 4;

    float acc[4][4];
#pragma unroll
    for (int i = 0; i < 4; i++)
#pragma unroll
        for (int jj = 0; jj < 4; jj++) acc[i][jj] = 0.f;

#pragma unroll 1
    for (int k0 = 0; k0 < K; k0 += 16) {
        float4 av = *(const float4*)&A[(size_t)(m0 + lr) * K + k0 + lc];
        float4 bv = *(const float4*)&B[(size_t)(n0 + lr) * K + k0 + lc];
        __syncthreads();
        As[lc + 0][lr] = av.x; As[lc + 1][lr] = av.y; As[lc + 2][lr] = av.z; As[lc + 3][lr] = av.w;
        Bs[lc + 0][lr] = bv.x; Bs[lc + 1][lr] = bv.y; Bs[lc + 2][lr] = bv.z; Bs[lc + 3][lr] = bv.w;
        __syncthreads();
#pragma unroll
        for (int k = 0; k < 16; k++) {
            float4 a = *(const float4*)&As[k][ty * 4];
            float4 b = *(const float4*)&Bs[k][tx * 4];
            acc[0][0] += a.x * b.x; acc[0][1] += a.x * b.y; acc[0][2] += a.x * b.z; acc[0][3] += a.x * b.w;
            acc[1][0] += a.y * b.x; acc[1][1] += a.y * b.y; acc[1][2] += a.y * b.z; acc[1][3] += a.y * b.w;
            acc[2][0] += a.z * b.x; acc[2][1] += a.z * b.y; acc[2][2] += a.z * b.z; acc[2][3] += a.z * b.w;
            acc[3][0] += a.w * b.x; acc[3][1] += a.w * b.y; acc[3][2] += a.w * b.z; acc[3][3] += a.w * b.w;
        }
    }
#pragma unroll
    for (int i = 0; i < 4; i++) {
        float4 v = make_float4(acc[i][0], acc[i][1], acc[i][2], acc[i][3]);
        *(float4*)&C[(size_t)(m0 + ty * 4 + i) * N + n0 + tx * 4] = v;
    }
}

// ---------------- host orchestration: 8 graph nodes ----------------
extern "C" void kernel_launch(void* const* d_in, const int* in_sizes, int n_in,
                              void* d_out, int out_size)
{
    (void)in_sizes; (void)n_in; (void)out_size;

    const float* x     = (const float*)d_in[0];
    const float* y     = (const float*)d_in[1];
    const int*   force = (const int*)  d_in[2];
    const float* eWih0 = (const float*)d_in[3];
    const float* eWhh0 = (const float*)d_in[4];
    const float* ebih0 = (const float*)d_in[5];
    const float* ebhh0 = (const float*)d_in[6];
    const float* eWih  = (const float*)d_in[7];
    const float* eWhh  = (const float*)d_in[8];
    const float* ebih  = (const float*)d_in[9];
    const float* ebhh  = (const float*)d_in[10];
    const float* dWih0 = (const float*)d_in[11];
    const float* dWhh0 = (const float*)d_in[12];
    const float* dbih0 = (const float*)d_in[13];
    const float* dbhh0 = (const float*)d_in[14];
    const float* dWih  = (const float*)d_in[15];
    const float* dWhh  = (const float*)d_in[16];
    const float* dbih  = (const float*)d_in[17];
    const float* dbhh  = (const float*)d_in[18];
    const float* Wu    = (const float*)d_in[19];
    const float* bu    = (const float*)d_in[20];
    float* out = (float*)d_out;

    float* xg;
    cudaGetSymbolAddress((void**)&xg, g_xg);

    const size_t WSTRIDE = (size_t)GDIM * HDIM;
    const dim3 gBig(GDIM / 64, (BDIM * TDIM) / 64);
    const dim3 gHoist(HDIM / 8, (BDIM * TDIM) / 128);

    // split all recurrent + hoist weights into packed bf16 hi/lo records
    prep_w<<<2048, 256>>>(eWhh0, eWhh, eWhh + WSTRIDE,
                          dWhh0, dWih, dWih + WSTRIDE,
                          dWhh, dWhh + WSTRIDE,
                          eWih, eWih + WSTRIDE);

    // encoder layer 0 (input hoist is tiny K=32 fp32 GEMM)
    gemm_hoist<<<gBig, 256>>>(x, eWih0, IDIM, xg, BDIM * TDIM, GDIM);
    enc_layer_kernel<<<NBLK, NTHR>>>(W_EWH0, 0, ebih0, ebhh0, /*write_seq=*/1);
    // encoder layer 1
    hoist_mma<<<gHoist, NTHR>>>(W_HWI1);
    enc_layer_kernel<<<NBLK, NTHR>>>(W_EWH1, 1, ebih, ebhh, /*write_seq=*/1);
    // encoder layer 2
    hoist_mma<<<gHoist, NTHR>>>(W_HWI2);
    enc_layer_kernel<<<NBLK, NTHR>>>(W_EWH2, 2, ebih + GDIM, ebhh + GDIM, /*write_seq=*/0);

    // decoder (persistent, all 511 steps)
    dec_kernel<<<NBLK, NTHR>>>(dWih0, dbih0, dbhh0, dbih, dbhh,
                               Wu, bu, y, force, out);
}

// round 14
// speedup vs baseline: 7.1259x; 1.3597x over previous
#include <cuda_runtime.h>
#include <cuda_bf16.h>
#include <math.h>
#include <stdint.h>
#include <stddef.h>

#define BDIM 128
#define TDIM 512
#define IDIM 32
#define HDIM 1024
#define GDIM 4096
#define BH   (BDIM*HDIM)
#define NBLK 128
#define NTHR 512            // 2 K-groups x 8 warps
#define MSZ  4194304        // 4096*1024 elements per weight matrix
#define WREC 1048576        // uint4 records per weight matrix (MSZ/4)
#define HREC 32768          // uint4 records per H buffer (128*1024/4)

// weight slots in the packed store
#define W_EWH0 0
#define W_EWH1 1
#define W_EWH2 2
#define W_DWH0 3
#define W_DWI1 4
#define W_DWI2 5
#define W_DWH1 6
#define W_DWH2 7
#define W_HWI1 8
#define W_HWI2 9
#define NWMAT  10

// ---------------- static device scratch (no allocations anywhere) ----------------
// Packed record layout (16 B per lane-record = 4 elements' hi+lo):
//   bf16[0..1]=hi k-tile t0, bf16[2..3]=hi t1, bf16[4..5]=lo t0, bf16[6..7]=lo t1
static __device__ uint4 g_w4[(size_t)NWMAT * WREC];          // packed weights (160 MB)
static __device__ uint4 g_eh4[2][HREC];                      // encoder h ping-pong
static __device__ uint4 g_z4[HREC];                          // never written -> zeros
static __device__ uint4 g_dh4[2][3][HREC];                   // decoder h [par][layer]
static __device__ uint4 g_s4[(size_t)TDIM * HREC];           // seq acts, slab-per-t (256 MB)
static __device__ float g_h2f[BH];                           // decoder top-layer h fp32 (head)
static __device__ float g_xg[(size_t)TDIM * GDIM * BDIM];    // input-gate preacts [t][g][u][b] (1 GB)
static __device__ float g_cT[3 * BH];                        // encoder final c
static __device__ float g_xfeed[BDIM];
static __device__ unsigned g_count = 0;
static __device__ unsigned g_gen = 0;

// xg address: [t][gate q][unit u][batch b]  -> lane-consecutive in b
__device__ __forceinline__ size_t XG(int t, int q, int u, int b) {
    return ((((size_t)t << 12) + ((size_t)q << 10) + (size_t)u) << 7) + (size_t)b;
}

// ---------------- software grid barrier (all NBLK blocks resident) ----------------
__device__ __forceinline__ void gsync() {
    __syncthreads();
    if (threadIdx.x == 0) {
        unsigned gen = *((volatile unsigned*)&g_gen);
        __threadfence();
        if (atomicAdd(&g_count, 1u) == gridDim.x - 1) {
            atomicExch(&g_count, 0u);
            __threadfence();
            *((volatile unsigned*)&g_gen) = gen + 1u;
        } else {
            while (*((volatile unsigned*)&g_gen) == gen) __nanosleep(32);
        }
        __threadfence();
    }
    __syncthreads();
}

__device__ __forceinline__ float sigm(float x) { return 1.f / (1.f + expf(-x)); }

#define MMA16816(C, A0, A1, A2, A3, B0, B1) \
    asm volatile("mma.sync.aligned.m16n8k16.row.col.f32.bf16.bf16.f32 " \
        "{%0,%1,%2,%3}, {%4,%5,%6,%7}, {%8,%9}, {%0,%1,%2,%3};" \
        : "+f"((C)[0]), "+f"((C)[1]), "+f"((C)[2]), "+f"((C)[3]) \
        : "r"(A0), "r"(A1), "r"(A2), "r"(A3), "r"(B0), "r"(B1))

// write one fp32 value as packed hi/lo bf16 into an H-style record array
__device__ __forceinline__ void put_h(uint4* H4, int b, int u, float hn) {
    __nv_bfloat16 hh = __float2bfloat16(hn);
    __nv_bfloat16 hl = __float2bfloat16(hn - __bfloat162float(hh));
    const int t01 = (u >> 3) & 1, half = u & 1;
    __nv_bfloat16* p = (__nv_bfloat16*)(H4 + ((size_t)((b >> 3) * 64 + (u >> 4)) * 32
                                              + (b & 7) * 4 + ((u & 7) >> 1)));
    p[t01 * 2 + half]     = hh;
    p[4 + t01 * 2 + half] = hl;
}

// ---------------- weight prep: fp32 -> packed hi/lo records ----------------
__global__ void prep_w(const float* p0, const float* p1, const float* p2, const float* p3,
                       const float* p4, const float* p5, const float* p6, const float* p7,
                       const float* p8, const float* p9)
{
    for (size_t i = (size_t)blockIdx.x * blockDim.x + threadIdx.x;
         i < (size_t)NWMAT * MSZ; i += (size_t)gridDim.x * blockDim.x) {
        int m = (int)(i >> 22);
        int e = (int)(i & (MSZ - 1));
        const float* src;
        switch (m) {
            case 0: src = p0; break; case 1: src = p1; break;
            case 2: src = p2; break; case 3: src = p3; break;
            case 4: src = p4; break; case 5: src = p5; break;
            case 6: src = p6; break; case 7: src = p7; break;
            case 8: src = p8; break; default: src = p9; break;
        }
        float v = src[e];
        __nv_bfloat16 h = __float2bfloat16(v);
        __nv_bfloat16 l = __float2bfloat16(v - __bfloat162float(h));
        int row = e >> 10, k = e & 1023;
        uint4* rec = g_w4 + (size_t)m * WREC
                   + ((size_t)((row >> 3) * 64 + (k >> 4)) * 32
                      + (row & 7) * 4 + ((k & 7) >> 1));
        __nv_bfloat16* p = (__nv_bfloat16*)rec;
        const int t01 = (k >> 3) & 1, half = k & 1;
        p[t01 * 2 + half]     = h;
        p[4 + t01 * 2 + half] = l;
    }
}

// ---------------- block MMA over one K-half: C[32 Wrows, 128 rows] += W @ H^T ----------------
__device__ __forceinline__ void accum_mma(
    const uint4* __restrict__ W4, const uint4* __restrict__ H4,
    float C[4][4], int u0, int kg)
{
    const int tid = threadIdx.x;
    const int w8 = (tid >> 5) & 7, lane = tid & 31;
    const int q0 = (w8 & 1) * 2, q1 = q0 + 1;
    const uint32_t rb0 = (uint32_t)(q0 * 128 + (u0 >> 3)) * 2048u + (uint32_t)lane;
    const uint32_t rb1 = (uint32_t)(q1 * 128 + (u0 >> 3)) * 2048u + (uint32_t)lane;
    uint32_t hb[4];
#pragma unroll
    for (int j = 0; j < 4; j++)
        hb[j] = (uint32_t)((w8 >> 1) * 4 + j) * 2048u + (uint32_t)lane;

#pragma unroll 2
    for (int kt2 = 0; kt2 < 32; kt2++) {
        const uint32_t ko = (uint32_t)(kg * 32 + kt2) * 32u;
        uint4 wa = W4[rb0 + ko];     // A frags gate q0
        uint4 wb = W4[rb1 + ko];     // A frags gate q1
#pragma unroll
        for (int j = 0; j < 4; j++) {
            uint4 h = H4[hb[j] + ko];
            MMA16816(C[j], wa.x, wb.x, wa.y, wb.y, h.x, h.y);  // hi*hi
            MMA16816(C[j], wa.x, wb.x, wa.y, wb.y, h.z, h.w);  // hi*lo
            MMA16816(C[j], wa.z, wb.z, wa.w, wb.w, h.x, h.y);  // lo*hi
        }
    }
}

// store C fragments into gates smem [r_local 32][row 128]; r_local = q*8 + unit_off
__device__ __forceinline__ void store_C(float C[4][4], float (*gs)[132])
{
    const int tid = threadIdx.x;
    const int w8 = (tid >> 5) & 7, lane = tid & 31;
    const int g = lane >> 2, tg = lane & 3;
    const int r0 = (w8 & 1) * 16 + g;
    const int r1 = r0 + 8;
#pragma unroll
    for (int j = 0; j < 4; j++) {
        const int cb = (w8 >> 1) * 32 + j * 8 + 2 * tg;
        gs[r0][cb]     = C[j][0];
        gs[r0][cb + 1] = C[j][1];
        gs[r1][cb]     = C[j][2];
        gs[r1][cb + 1] = C[j][3];
    }
}

// ---------------- bf16 MMA hoist GEMM: xg[t-slab] = W @ Sact[t-slab]^T ----------------
__global__ void __launch_bounds__(256, 2) hoist_mma(int wslot)
{
    __shared__ float gates_s[32][132];
    const int u0 = blockIdx.x * 8;
    const int t = blockIdx.y;

    float C[4][4];
#pragma unroll
    for (int a = 0; a < 4; a++)
#pragma unroll
        for (int b = 0; b < 4; b++) C[a][b] = 0.f;

    accum_mma(g_w4 + (size_t)wslot * WREC, g_s4 + (size_t)t * HREC, C, u0, 0);
    accum_mma(g_w4 + (size_t)wslot * WREC, g_s4 + (size_t)t * HREC, C, u0, 1);
    store_C(C, gates_s);
    __syncthreads();

    const int tid = threadIdx.x;
#pragma unroll
    for (int pass = 0; pass < 16; pass++) {
        const int idx = pass * 256 + tid;
        const int b = idx & 127, r = idx >> 7;       // r = q*8 + uo
        g_xg[XG(t, r >> 3, u0 + (r & 7), b)] = gates_s[r][b];
    }
}

// ---------------- persistent encoder layer ----------------
__global__ void __launch_bounds__(NTHR, 1) enc_layer_kernel(
    int wslot, int dslot,
    const float* __restrict__ bih, const float* __restrict__ bhh,
    int write_seq)
{
    __shared__ float gates_s[2][32][132];
    const int tid = threadIdx.x;
    const int u0 = blockIdx.x * 8;
    const int kg = tid >> 8;
    const int j = (tid >> 5) & 7, bl = tid & 31;
    const int u = u0 + j;
    const uint4* W4 = g_w4 + (size_t)wslot * WREC;

    float bs[4];
#pragma unroll
    for (int q = 0; q < 4; q++) bs[q] = bih[(q << 10) + u] + bhh[(q << 10) + u];

    float cl[2] = {0.f, 0.f};
    float hl[2] = {0.f, 0.f};

#pragma unroll 1
    for (int t = 0; t < TDIM; t++) {
        float C[4][4];
#pragma unroll
        for (int a = 0; a < 4; a++)
#pragma unroll
            for (int b = 0; b < 4; b++) C[a][b] = 0.f;

        const uint4* H = t ? g_eh4[t & 1] : g_z4;
        accum_mma(W4, H, C, u0, kg);
        store_C(C, gates_s[kg]);
        __syncthreads();

        const int wp = (t + 1) & 1;
#pragma unroll
        for (int i = 0; i < 2; i++) {
            const int b = bl + 32 * i + 64 * kg;
            float ip = gates_s[0][j][b]      + gates_s[1][j][b]      + g_xg[XG(t, 0, u, b)] + bs[0];
            float fp = gates_s[0][8 + j][b]  + gates_s[1][8 + j][b]  + g_xg[XG(t, 1, u, b)] + bs[1];
            float gp = gates_s[0][16 + j][b] + gates_s[1][16 + j][b] + g_xg[XG(t, 2, u, b)] + bs[2];
            float op = gates_s[0][24 + j][b] + gates_s[1][24 + j][b] + g_xg[XG(t, 3, u, b)] + bs[3];
            float cn = sigm(fp) * cl[i] + sigm(ip) * tanhf(gp);
            float hn = sigm(op) * tanhf(cn);
            cl[i] = cn; hl[i] = hn;
            put_h(g_eh4[wp], b, u, hn);
            if (write_seq)
                put_h(g_s4 + (size_t)t * HREC, b, u, hn);
        }
        gsync();
    }
    // export final states for the decoder
#pragma unroll
    for (int i = 0; i < 2; i++) {
        const int b = bl + 32 * i + 64 * kg;
        g_cT[dslot * BH + b * HDIM + u] = cl[i];
        put_h(&g_dh4[0][dslot][0], b, u, hl[i]);
    }
}

// ---------------- persistent decoder ----------------
__global__ void __launch_bounds__(NTHR, 1) dec_kernel(
    const float* __restrict__ dWih0,
    const float* __restrict__ dbih0, const float* __restrict__ dbhh0,
    const float* __restrict__ dbih,  const float* __restrict__ dbhh,
    const float* __restrict__ Wu,    const float* __restrict__ bu,
    const float* __restrict__ y,     const int* __restrict__ force,
    float* __restrict__ out)
{
    __shared__ float gates_s[2][32][132];
    __shared__ float red2[16];
    const int tid = threadIdx.x;
    const int u0 = blockIdx.x * 8;
    const int kg = tid >> 8;
    const int j = (tid >> 5) & 7, bl = tid & 31;
    const int u = u0 + j;

    float bs0[4], bs1[4], bs2[4], wc0[4];
#pragma unroll
    for (int q = 0; q < 4; q++) {
        const int g = (q << 10) + u;
        bs0[q] = dbih0[g] + dbhh0[g];
        bs1[q] = dbih[g] + dbhh[g];
        bs2[q] = dbih[GDIM + g] + dbhh[GDIM + g];
        wc0[q] = dWih0[g];
    }
    float c0[2], c1[2], c2[2];
#pragma unroll
    for (int i = 0; i < 2; i++) {
        const int b = bl + 32 * i + 64 * kg;
        c0[i] = g_cT[0 * BH + b * HDIM + u];
        c1[i] = g_cT[1 * BH + b * HDIM + u];
        c2[i] = g_cT[2 * BH + b * HDIM + u];
    }
    if (blockIdx.x == 0 && tid < BDIM) {
        g_xfeed[tid] = y[(size_t)tid * TDIM];
        out[(size_t)tid * TDIM] = 0.f;     // output[:,0] = 0
    }
    gsync();

#pragma unroll 1
    for (int s = 0; s < TDIM - 1; s++) {
        const int p = s & 1;
        float C[4][4];

        // ----- layer 0: gates = h0 @ Whh0^T (+ xfeed*Wih0 + b) -----
#pragma unroll
        for (int a = 0; a < 4; a++)
#pragma unroll
            for (int b = 0; b < 4; b++) C[a][b] = 0.f;
        accum_mma(g_w4 + (size_t)W_DWH0 * WREC, &g_dh4[p][0][0], C, u0, kg);
        store_C(C, gates_s[kg]);
        __syncthreads();
#pragma unroll
        for (int i = 0; i < 2; i++) {
            const int b = bl + 32 * i + 64 * kg;
            const float xf = g_xfeed[b];
            float ip = gates_s[0][j][b]      + gates_s[1][j][b]      + xf * wc0[0] + bs0[0];
            float fp = gates_s[0][8 + j][b]  + gates_s[1][8 + j][b]  + xf * wc0[1] + bs0[1];
            float gp = gates_s[0][16 + j][b] + gates_s[1][16 + j][b] + xf * wc0[2] + bs0[2];
            float op = gates_s[0][24 + j][b] + gates_s[1][24 + j][b] + xf * wc0[3] + bs0[3];
            float cn = sigm(fp) * c0[i] + sigm(ip) * tanhf(gp);
            float hn = sigm(op) * tanhf(cn);
            c0[i] = cn;
            put_h(&g_dh4[p ^ 1][0][0], b, u, hn);
        }
        gsync();

        // ----- layer 1: gates = h0_new @ Wih1^T + h1 @ Whh1^T -----
#pragma unroll
        for (int a = 0; a < 4; a++)
#pragma unroll
            for (int b = 0; b < 4; b++) C[a][b] = 0.f;
        accum_mma(g_w4 + (size_t)W_DWI1 * WREC, &g_dh4[p ^ 1][0][0], C, u0, kg);
        accum_mma(g_w4 + (size_t)W_DWH1 * WREC, &g_dh4[p][1][0], C, u0, kg);
        store_C(C, gates_s[kg]);
        __syncthreads();
#pragma unroll
        for (int i = 0; i < 2; i++) {
            const int b = bl + 32 * i + 64 * kg;
            float ip = gates_s[0][j][b]      + gates_s[1][j][b]      + bs1[0];
            float fp = gates_s[0][8 + j][b]  + gates_s[1][8 + j][b]  + bs1[1];
            float gp = gates_s[0][16 + j][b] + gates_s[1][16 + j][b] + bs1[2];
            float op = gates_s[0][24 + j][b] + gates_s[1][24 + j][b] + bs1[3];
            float cn = sigm(fp) * c1[i] + sigm(ip) * tanhf(gp);
            float hn = sigm(op) * tanhf(cn);
            c1[i] = cn;
            put_h(&g_dh4[p ^ 1][1][0], b, u, hn);
        }
        gsync();

        // ----- layer 2 -----
#pragma unroll
        for (int a = 0; a < 4; a++)
#pragma unroll
            for (int b = 0; b < 4; b++) C[a][b] = 0.f;
        accum_mma(g_w4 + (size_t)W_DWI2 * WREC, &g_dh4[p ^ 1][1][0], C, u0, kg);
        accum_mma(g_w4 + (size_t)W_DWH2 * WREC, &g_dh4[p][2][0], C, u0, kg);
        store_C(C, gates_s[kg]);
        __syncthreads();
#pragma unroll
        for (int i = 0; i < 2; i++) {
            const int b = bl + 32 * i + 64 * kg;
            float ip = gates_s[0][j][b]      + gates_s[1][j][b]      + bs2[0];
            float fp = gates_s[0][8 + j][b]  + gates_s[1][8 + j][b]  + bs2[1];
            float gp = gates_s[0][16 + j][b] + gates_s[1][16 + j][b] + bs2[2];
            float op = gates_s[0][24 + j][b] + gates_s[1][24 + j][b] + bs2[3];
            float cn = sigm(fp) * c2[i] + sigm(ip) * tanhf(gp);
            float hn = sigm(op) * tanhf(cn);
            c2[i] = cn;
            g_h2f[b * HDIM + u] = hn;
            put_h(&g_dh4[p ^ 1][2][0], b, u, hn);
        }
        gsync();

        // ----- output head + teacher forcing: block b handles batch row b -----
        {
            const float* hr = g_h2f + (size_t)blockIdx.x * HDIM;
            float a = 0.f;
#pragma unroll 2
            for (int k = tid; k < HDIM; k += NTHR) a += hr[k] * Wu[k];
#pragma unroll
            for (int o = 16; o; o >>= 1) a += __shfl_xor_sync(0xFFFFFFFFu, a, o);
            if ((tid & 31) == 0) red2[tid >> 5] = a;
            __syncthreads();
            if (tid == 0) {
                float ov = bu[0];
#pragma unroll
                for (int ww = 0; ww < 16; ww++) ov += red2[ww];
                out[(size_t)blockIdx.x * TDIM + s + 1] = ov;
                g_xfeed[blockIdx.x] = (force[s] > 0) ? y[(size_t)blockIdx.x * TDIM + s + 1] : ov;
            }
        }
        gsync();
    }
}

// ---------------- fp32 NT GEMM for the tiny K=32 layer-0 hoist ----------------
// writes xg in [t][q][u][b] layout
__global__ void __launch_bounds__(256) gemm_hoist(
    const float* __restrict__ A, const float* __restrict__ B, int K)
{
    __shared__ float As[16][68];
    __shared__ float Bs[16][68];
    const int tid = threadIdx.x;
    const int tx = tid & 15, ty = tid >> 4;
    const int m0 = blockIdx.y * 64, n0 = blockIdx.x * 64;
    const int lr = tid >> 2;
    const int lc = (tid & 3) * 4;

    float acc[4][4];
#pragma unroll
    for (int i = 0; i < 4; i++)
#pragma unroll
        for (int jj = 0; jj < 4; jj++) acc[i][jj] = 0.f;

#pragma unroll 1
    for (int k0 = 0; k0 < K; k0 += 16) {
        float4 av = *(const float4*)&A[(size_t)(m0 + lr) * K + k0 + lc];
        float4 bv = *(const float4*)&B[(size_t)(n0 + lr) * K + k0 + lc];
        __syncthreads();
        As[lc + 0][lr] = av.x; As[lc + 1][lr] = av.y; As[lc + 2][lr] = av.z; As[lc + 3][lr] = av.w;
        Bs[lc + 0][lr] = bv.x; Bs[lc + 1][lr] = bv.y; Bs[lc + 2][lr] = bv.z; Bs[lc + 3][lr] = bv.w;
        __syncthreads();
#pragma unroll
        for (int k = 0; k < 16; k++) {
            float4 a = *(const float4*)&As[k][ty * 4];
            float4 b = *(const float4*)&Bs[k][tx * 4];
            acc[0][0] += a.x * b.x; acc[0][1] += a.x * b.y; acc[0][2] += a.x * b.z; acc[0][3] += a.x * b.w;
            acc[1][0] += a.y * b.x; acc[1][1] += a.y * b.y; acc[1][2] += a.y * b.z; acc[1][3] += a.y * b.w;
            acc[2][0] += a.z * b.x; acc[2][1] += a.z * b.y; acc[2][2] += a.z * b.z; acc[2][3] += a.z * b.w;
            acc[3][0] += a.w * b.x; acc[3][1] += a.w * b.y; acc[3][2] += a.w * b.z; acc[3][3] += a.w * b.w;
        }
    }
#pragma unroll
    for (int i = 0; i < 4; i++) {
        const int m = m0 + ty * 4 + i;               // m = b*TDIM + t
        const int bb = m >> 9, t = m & 511;
#pragma unroll
        for (int jj = 0; jj < 4; jj++) {
            const int n = n0 + tx * 4 + jj;          // n = q*1024 + u
            g_xg[XG(t, n >> 10, n & 1023, bb)] = acc[i][jj];
        }
    }
}

// ---------------- host orchestration: 8 graph nodes ----------------
extern "C" void kernel_launch(void* const* d_in, const int* in_sizes, int n_in,
                              void* d_out, int out_size)
{
    (void)in_sizes; (void)n_in; (void)out_size;

    const float* x     = (const float*)d_in[0];
    const float* y     = (const float*)d_in[1];
    const int*   force = (const int*)  d_in[2];
    const float* eWih0 = (const float*)d_in[3];
    const float* eWhh0 = (const float*)d_in[4];
    const float* ebih0 = (const float*)d_in[5];
    const float* ebhh0 = (const float*)d_in[6];
    const float* eWih  = (const float*)d_in[7];
    const float* eWhh  = (const float*)d_in[8];
    const float* ebih  = (const float*)d_in[9];
    const float* ebhh  = (const float*)d_in[10];
    const float* dWih0 = (const float*)d_in[11];
    const float* dWhh0 = (const float*)d_in[12];
    const float* dbih0 = (const float*)d_in[13];
    const float* dbhh0 = (const float*)d_in[14];
    const float* dWih  = (const float*)d_in[15];
    const float* dWhh  = (const float*)d_in[16];
    const float* dbih  = (const float*)d_in[17];
    const float* dbhh  = (const float*)d_in[18];
    const float* Wu    = (const float*)d_in[19];
    const float* bu    = (const float*)d_in[20];
    float* out = (float*)d_out;

    const size_t WSTRIDE = (size_t)GDIM * HDIM;
    const dim3 gBig(GDIM / 64, (BDIM * TDIM) / 64);
    const dim3 gHoist(HDIM / 8, TDIM);

    // split all recurrent + hoist weights into packed bf16 hi/lo records
    prep_w<<<2048, 256>>>(eWhh0, eWhh, eWhh + WSTRIDE,
                          dWhh0, dWih, dWih + WSTRIDE,
                          dWhh, dWhh + WSTRIDE,
                          eWih, eWih + WSTRIDE);

    // encoder layer 0 (input hoist is tiny K=32 fp32 GEMM)
    gemm_hoist<<<gBig, 256>>>(x, eWih0, IDIM);
    enc_layer_kernel<<<NBLK, NTHR>>>(W_EWH0, 0, ebih0, ebhh0, /*write_seq=*/1);
    // encoder layer 1
    hoist_mma<<<gHoist, 256>>>(W_HWI1);
    enc_layer_kernel<<<NBLK, NTHR>>>(W_EWH1, 1, ebih, ebhh, /*write_seq=*/1);
    // encoder layer 2
    hoist_mma<<<gHoist, 256>>>(W_HWI2);
    enc_layer_kernel<<<NBLK, NTHR>>>(W_EWH2, 2, ebih + GDIM, ebhh + GDIM, /*write_seq=*/0);

    // decoder (persistent, all 511 steps)
    dec_kernel<<<NBLK, NTHR>>>(dWih0, dbih0, dbhh0, dbih, dbhh,
                               Wu, bu, y, force, out);
}